// round 1
// baseline (speedup 1.0000x reference)
#include <cuda_runtime.h>
#include <cuda_bf16.h>
#include <math.h>

// Problem constants (fixed by the dataset)
#define B_SZ   64
#define FULLN  513
#define E_SZ   768
#define NB     32
#define GRID   8
#define NHEAD  12
#define HDIM   64
#define NP     (B_SZ * NB)        // 2048 sample points total
#define KV_N   (2 * E_SZ)         // 1536

// -------- scratch (device globals; no allocation allowed) --------
__device__ float g_S  [NP * E_SZ];     // raw trilinear samples    (2048 x 768)
__device__ float g_S2 [NP * E_SZ];     // after sample_proj        (2048 x 768)
__device__ float g_KV [NP * KV_N];     // k (cols 0..767) | v (768..1535)
__device__ float g_Q  [B_SZ * E_SZ];   // q per batch
__device__ float g_CTX[B_SZ * E_SZ];   // attention context
__device__ float g_AO [B_SZ * E_SZ];   // out_proj result

// ---------------------------------------------------------------
// 1) Trilinear border sampling: one block per (b, p)
// ---------------------------------------------------------------
__global__ __launch_bounds__(256)
void gather_kernel(const float* __restrict__ x,
                   const float* __restrict__ base_coords,
                   const float* __restrict__ offsets,
                   float* __restrict__ S)
{
    const int bp = blockIdx.x;         // 0..2047
    const int b  = bp >> 5;
    const int p  = bp & 31;

    float cx = fminf(fmaxf(base_coords[p*3+0] + offsets[bp*3+0], -1.f), 1.f);
    float cy = fminf(fmaxf(base_coords[p*3+1] + offsets[bp*3+1], -1.f), 1.f);
    float cz = fminf(fmaxf(base_coords[p*3+2] + offsets[bp*3+2], -1.f), 1.f);

    float ix = (cx + 1.0f) * 0.5f * (GRID - 1);
    float iy = (cy + 1.0f) * 0.5f * (GRID - 1);
    float iz = (cz + 1.0f) * 0.5f * (GRID - 1);

    float fx = floorf(ix), fy = floorf(iy), fz = floorf(iz);
    float wx = ix - fx, wy = iy - fy, wz = iz - fz;

    int x0 = (int)fx; int y0 = (int)fy; int z0 = (int)fz;
    x0 = min(max(x0, 0), GRID-1); y0 = min(max(y0, 0), GRID-1); z0 = min(max(z0, 0), GRID-1);
    int x1 = min(x0 + 1, GRID-1);
    int y1 = min(y0 + 1, GRID-1);
    int z1 = min(z0 + 1, GRID-1);

    // token index for (z,y,x): 1 + (z*8+y)*8+x ; channel-contiguous rows in x
    const float* xb = x + ((size_t)b * FULLN + 1) * E_SZ;

    const int i000 = (((z0*GRID)+y0)*GRID + x0) * E_SZ;
    const int i001 = (((z0*GRID)+y0)*GRID + x1) * E_SZ;
    const int i010 = (((z0*GRID)+y1)*GRID + x0) * E_SZ;
    const int i011 = (((z0*GRID)+y1)*GRID + x1) * E_SZ;
    const int i100 = (((z1*GRID)+y0)*GRID + x0) * E_SZ;
    const int i101 = (((z1*GRID)+y0)*GRID + x1) * E_SZ;
    const int i110 = (((z1*GRID)+y1)*GRID + x0) * E_SZ;
    const int i111 = (((z1*GRID)+y1)*GRID + x1) * E_SZ;

    const float w000 = (1-wz)*(1-wy)*(1-wx);
    const float w001 = (1-wz)*(1-wy)*wx;
    const float w010 = (1-wz)*wy*(1-wx);
    const float w011 = (1-wz)*wy*wx;
    const float w100 = wz*(1-wy)*(1-wx);
    const float w101 = wz*(1-wy)*wx;
    const float w110 = wz*wy*(1-wx);
    const float w111 = wz*wy*wx;

    float* out = S + (size_t)bp * E_SZ;
    for (int c = threadIdx.x; c < E_SZ; c += blockDim.x) {
        float v = w000 * xb[i000 + c]
                + w001 * xb[i001 + c]
                + w010 * xb[i010 + c]
                + w011 * xb[i011 + c]
                + w100 * xb[i100 + c]
                + w101 * xb[i101 + c]
                + w110 * xb[i110 + c]
                + w111 * xb[i111 + c];
        out[c] = v;
    }
}

// ---------------------------------------------------------------
// 2) Generic NT SGEMM: C[m,n] = sum_k A[m,k] * B[n,k] + bias[n]
//    64x64 block tile, 4x4 per thread, BK=16, 256 threads
// ---------------------------------------------------------------
#define BM 64
#define BN 64
#define BK 16
#define TM 4
#define TN 4

__global__ __launch_bounds__(256)
void sgemm_nt(int M, int N, int K,
              const float* __restrict__ A,
              const float* __restrict__ B,
              const float* __restrict__ bias,
              float* __restrict__ C)
{
    __shared__ float As[BK][BM + 1];
    __shared__ float Bs[BK][BN + 1];

    const int bm = blockIdx.y * BM;
    const int bn = blockIdx.x * BN;
    const int tid = threadIdx.x;
    const int tx = tid % (BN / TN);   // 0..15
    const int ty = tid / (BN / TN);   // 0..15

    float acc[TM][TN];
    #pragma unroll
    for (int i = 0; i < TM; i++)
        #pragma unroll
        for (int j = 0; j < TN; j++) acc[i][j] = 0.f;

    for (int k0 = 0; k0 < K; k0 += BK) {
        // load A tile: BM x BK
        #pragma unroll
        for (int i = tid; i < BM * BK; i += 256) {
            int m = i / BK, k = i % BK;
            As[k][m] = A[(size_t)(bm + m) * K + k0 + k];
        }
        // load B tile: BN x BK
        #pragma unroll
        for (int i = tid; i < BN * BK; i += 256) {
            int n = i / BK, k = i % BK;
            Bs[k][n] = B[(size_t)(bn + n) * K + k0 + k];
        }
        __syncthreads();

        #pragma unroll
        for (int kk = 0; kk < BK; kk++) {
            float a[TM], bb[TN];
            #pragma unroll
            for (int i = 0; i < TM; i++) a[i]  = As[kk][ty * TM + i];
            #pragma unroll
            for (int j = 0; j < TN; j++) bb[j] = Bs[kk][tx * TN + j];
            #pragma unroll
            for (int i = 0; i < TM; i++)
                #pragma unroll
                for (int j = 0; j < TN; j++)
                    acc[i][j] = fmaf(a[i], bb[j], acc[i][j]);
        }
        __syncthreads();
    }

    #pragma unroll
    for (int i = 0; i < TM; i++) {
        int m = bm + ty * TM + i;
        if (m >= M) continue;
        #pragma unroll
        for (int j = 0; j < TN; j++) {
            int n = bn + tx * TN + j;
            C[(size_t)m * N + n] = acc[i][j] + bias[n];
        }
    }
}

// ---------------------------------------------------------------
// 3) Attention: one block per batch. 384 threads = 12 warps (1/head)
// ---------------------------------------------------------------
__global__ __launch_bounds__(384)
void attention_kernel(const float* __restrict__ q,
                      const float* __restrict__ kv,
                      float* __restrict__ ctx)
{
    const int b = blockIdx.x;
    const int t = threadIdx.x;

    __shared__ float q_sh[E_SZ];
    __shared__ float attn_sh[NHEAD][NB];

    for (int c = t; c < E_SZ; c += 384) q_sh[c] = q[(size_t)b * E_SZ + c];
    __syncthreads();

    const int h = t >> 5;     // warp id = head
    const int p = t & 31;     // lane = point

    // score[h][p] = q[h,:] . k[p,h,:] / 8
    const float* krow = kv + ((size_t)(b * NB + p)) * KV_N + h * HDIM;
    float s = 0.f;
    #pragma unroll
    for (int d = 0; d < HDIM; d++) s = fmaf(q_sh[h * HDIM + d], krow[d], s);
    s *= 0.125f;   // 1/sqrt(64)

    // warp softmax over 32 points
    float m = s;
    #pragma unroll
    for (int o = 16; o > 0; o >>= 1) m = fmaxf(m, __shfl_xor_sync(0xffffffffu, m, o));
    float e = __expf(s - m);
    float sum = e;
    #pragma unroll
    for (int o = 16; o > 0; o >>= 1) sum += __shfl_xor_sync(0xffffffffu, sum, o);
    attn_sh[h][p] = e / sum;
    __syncthreads();

    // ctx[c] = sum_p attn[h(c)][p] * v[p][c]
    for (int c = t; c < E_SZ; c += 384) {
        const int hh = c >> 6;
        float acc = 0.f;
        #pragma unroll
        for (int pp = 0; pp < NB; pp++)
            acc = fmaf(attn_sh[hh][pp],
                       kv[((size_t)(b * NB + pp)) * KV_N + E_SZ + c], acc);
        ctx[(size_t)b * E_SZ + c] = acc;
    }
}

// ---------------------------------------------------------------
// 4) Broadcast + confidence scale: out[b,n,c] = ao[b,c]*conf[b]
// ---------------------------------------------------------------
__global__ __launch_bounds__(192)
void broadcast_kernel(const float* __restrict__ ao,
                      const float* __restrict__ conf,
                      float* __restrict__ out)
{
    const int n = blockIdx.x;       // 0..512
    const int b = blockIdx.y;       // 0..63
    const float cf = conf[b];
    const float4* src = (const float4*)(ao + (size_t)b * E_SZ);
    float4* dst = (float4*)(out + ((size_t)b * FULLN + n) * E_SZ);
    float4 v = src[threadIdx.x];
    v.x *= cf; v.y *= cf; v.z *= cf; v.w *= cf;
    dst[threadIdx.x] = v;
}

// ---------------------------------------------------------------
extern "C" void kernel_launch(void* const* d_in, const int* in_sizes, int n_in,
                              void* d_out, int out_size)
{
    const float* x           = (const float*)d_in[0];   // (64,513,768)
    const float* bio_embed   = (const float*)d_in[1];   // (64,768)
    const float* base_coords = (const float*)d_in[2];   // (32,3)
    const float* offsets     = (const float*)d_in[3];   // (64,32,3)
    const float* confidence  = (const float*)d_in[4];   // (64,1)
    const float* sample_w    = (const float*)d_in[5];   // (768,768)
    const float* sample_b    = (const float*)d_in[6];   // (768,)
    const float* in_proj_w   = (const float*)d_in[7];   // (2304,768)
    const float* in_proj_b   = (const float*)d_in[8];   // (2304,)
    const float* out_proj_w  = (const float*)d_in[9];   // (768,768)
    const float* out_proj_b  = (const float*)d_in[10];  // (768,)
    float* out = (float*)d_out;

    float *S, *S2, *KV, *Q, *CTX, *AO;
    cudaGetSymbolAddress((void**)&S,   g_S);
    cudaGetSymbolAddress((void**)&S2,  g_S2);
    cudaGetSymbolAddress((void**)&KV,  g_KV);
    cudaGetSymbolAddress((void**)&Q,   g_Q);
    cudaGetSymbolAddress((void**)&CTX, g_CTX);
    cudaGetSymbolAddress((void**)&AO,  g_AO);

    // 1) trilinear sample
    gather_kernel<<<NP, 256>>>(x, base_coords, offsets, S);

    // 2) sample_proj: S2 = S @ Ws^T + bs     (2048 x 768 x 768)
    {
        dim3 grid(E_SZ / BN, NP / BM);
        sgemm_nt<<<grid, 256>>>(NP, E_SZ, E_SZ, S, sample_w, sample_b, S2);
    }

    // 3) fused K,V proj: KV = S2 @ [Wk;Wv]^T + [bk;bv]   (2048 x 1536 x 768)
    {
        dim3 grid(KV_N / BN, NP / BM);
        sgemm_nt<<<grid, 256>>>(NP, KV_N, E_SZ,
                                S2, in_proj_w + (size_t)E_SZ * E_SZ,
                                in_proj_b + E_SZ, KV);
    }

    // 4) q proj: Q = bio_embed @ Wq^T + bq   (64 x 768 x 768)
    {
        dim3 grid(E_SZ / BN, B_SZ / BM);
        sgemm_nt<<<grid, 256>>>(B_SZ, E_SZ, E_SZ, bio_embed, in_proj_w, in_proj_b, Q);
    }

    // 5) attention -> CTX
    attention_kernel<<<B_SZ, 384>>>(Q, KV, CTX);

    // 6) out proj: AO = CTX @ Wo^T + bo      (64 x 768 x 768)
    {
        dim3 grid(E_SZ / BN, B_SZ / BM);
        sgemm_nt<<<grid, 256>>>(B_SZ, E_SZ, E_SZ, CTX, out_proj_w, out_proj_b, AO);
    }

    // 7) broadcast * confidence -> out (64,513,768)
    {
        dim3 grid(FULLN, B_SZ);
        broadcast_kernel<<<grid, 192>>>(AO, confidence, out);
    }
}

// round 2
// speedup vs baseline: 3.3937x; 3.3937x over previous
#include <cuda_runtime.h>
#include <math.h>

#define B_SZ   64
#define FULLN  513
#define E_SZ   768
#define NB     32
#define GRIDSZ 8
#define NHEAD  12
#define HDIM   64
#define NP     (B_SZ * NB)      // 2048

// ---------------- scratch (device globals) ----------------
__device__ float g_S  [NP * E_SZ];        // trilinear samples (2048 x 768)
__device__ float g_q  [B_SZ * E_SZ];      // q per batch (64 x 768)
__device__ float g_T  [E_SZ * E_SZ];      // t rows h*64+b (768 x 768)
__device__ float g_QH [E_SZ * E_SZ];      // qh' rows h*64+b
__device__ float g_WS [E_SZ * E_SZ];      // attn-weighted S, rows h*64+b
__device__ float g_U  [E_SZ * E_SZ];      // ws @ Ws^T + bs
__device__ float g_CTX[B_SZ * E_SZ];
__device__ float g_AO [B_SZ * E_SZ];
__device__ float g_P1 [12 * B_SZ * E_SZ];     // small-NT partials
__device__ float g_P2 [12 * 8 * 64 * 64];     // per-head ctx partials
__device__ float g_PB [2 * E_SZ * E_SZ];      // big-GEMM partials

// ---------------------------------------------------------------
// 1) Trilinear border sampling: one block per (b,p), float4 lanes
// ---------------------------------------------------------------
__global__ __launch_bounds__(192)
void gather_kernel(const float* __restrict__ x,
                   const float* __restrict__ bc,
                   const float* __restrict__ off,
                   float* __restrict__ S)
{
    const int bp = blockIdx.x;
    const int b  = bp >> 5;
    const int p  = bp & 31;

    float cx = fminf(fmaxf(bc[p*3+0] + off[bp*3+0], -1.f), 1.f);
    float cy = fminf(fmaxf(bc[p*3+1] + off[bp*3+1], -1.f), 1.f);
    float cz = fminf(fmaxf(bc[p*3+2] + off[bp*3+2], -1.f), 1.f);

    float ix = (cx + 1.0f) * 0.5f * (GRIDSZ - 1);
    float iy = (cy + 1.0f) * 0.5f * (GRIDSZ - 1);
    float iz = (cz + 1.0f) * 0.5f * (GRIDSZ - 1);

    float fx = floorf(ix), fy = floorf(iy), fz = floorf(iz);
    float wx = ix - fx, wy = iy - fy, wz = iz - fz;

    int x0 = min(max((int)fx, 0), GRIDSZ-1);
    int y0 = min(max((int)fy, 0), GRIDSZ-1);
    int z0 = min(max((int)fz, 0), GRIDSZ-1);
    int x1 = min(x0 + 1, GRIDSZ-1);
    int y1 = min(y0 + 1, GRIDSZ-1);
    int z1 = min(z0 + 1, GRIDSZ-1);

    const float* xb = x + ((size_t)b * FULLN + 1) * E_SZ;

    int idx[8];
    idx[0] = (((z0*GRIDSZ)+y0)*GRIDSZ + x0) * E_SZ;
    idx[1] = (((z0*GRIDSZ)+y0)*GRIDSZ + x1) * E_SZ;
    idx[2] = (((z0*GRIDSZ)+y1)*GRIDSZ + x0) * E_SZ;
    idx[3] = (((z0*GRIDSZ)+y1)*GRIDSZ + x1) * E_SZ;
    idx[4] = (((z1*GRIDSZ)+y0)*GRIDSZ + x0) * E_SZ;
    idx[5] = (((z1*GRIDSZ)+y0)*GRIDSZ + x1) * E_SZ;
    idx[6] = (((z1*GRIDSZ)+y1)*GRIDSZ + x0) * E_SZ;
    idx[7] = (((z1*GRIDSZ)+y1)*GRIDSZ + x1) * E_SZ;

    float w[8];
    w[0] = (1-wz)*(1-wy)*(1-wx);
    w[1] = (1-wz)*(1-wy)*wx;
    w[2] = (1-wz)*wy*(1-wx);
    w[3] = (1-wz)*wy*wx;
    w[4] = wz*(1-wy)*(1-wx);
    w[5] = wz*(1-wy)*wx;
    w[6] = wz*wy*(1-wx);
    w[7] = wz*wy*wx;

    float4* out = (float4*)(S + (size_t)bp * E_SZ);
    const int c = threadIdx.x;  // 0..191 float4 lanes
    float4 acc = make_float4(0.f,0.f,0.f,0.f);
    #pragma unroll
    for (int i = 0; i < 8; i++) {
        float4 v = ((const float4*)(xb + idx[i]))[c];
        acc.x = fmaf(w[i], v.x, acc.x);
        acc.y = fmaf(w[i], v.y, acc.y);
        acc.z = fmaf(w[i], v.z, acc.z);
        acc.w = fmaf(w[i], v.w, acc.w);
    }
    out[c] = acc;
}

// ---------------------------------------------------------------
// 2) Small-M NT GEMM with K-split: M=64 fixed, lda=ldb=768.
//    P[s][m*N + n] partials; grid (N/64, S)
// ---------------------------------------------------------------
__global__ __launch_bounds__(256)
void sgemm_nt64_split(int N, int kchunk,
                      const float* __restrict__ A,
                      const float* __restrict__ B,
                      float* __restrict__ P)
{
    __shared__ float As[16][65];
    __shared__ float Bs[16][65];
    const int bn = blockIdx.x * 64;
    const int k0base = blockIdx.y * kchunk;
    const int tid = threadIdx.x;
    const int tx = tid & 15, ty = tid >> 4;

    float acc[4][4] = {};
    for (int k0 = k0base; k0 < k0base + kchunk; k0 += 16) {
        #pragma unroll
        for (int i = tid; i < 1024; i += 256) {
            int m = i >> 4, k = i & 15;
            As[k][m] = A[(size_t)m * E_SZ + k0 + k];
        }
        #pragma unroll
        for (int i = tid; i < 1024; i += 256) {
            int n = i >> 4, k = i & 15;
            Bs[k][n] = B[(size_t)(bn + n) * E_SZ + k0 + k];
        }
        __syncthreads();
        #pragma unroll
        for (int kk = 0; kk < 16; kk++) {
            float a[4], bb[4];
            #pragma unroll
            for (int i = 0; i < 4; i++) a[i]  = As[kk][ty*4+i];
            #pragma unroll
            for (int j = 0; j < 4; j++) bb[j] = Bs[kk][tx*4+j];
            #pragma unroll
            for (int i = 0; i < 4; i++)
                #pragma unroll
                for (int j = 0; j < 4; j++)
                    acc[i][j] = fmaf(a[i], bb[j], acc[i][j]);
        }
        __syncthreads();
    }
    float* Pp = P + (size_t)blockIdx.y * 64 * N;
    #pragma unroll
    for (int i = 0; i < 4; i++)
        #pragma unroll
        for (int j = 0; j < 4; j++)
            Pp[(size_t)(ty*4+i) * N + bn + tx*4+j] = acc[i][j];
}

// reduce small-NT partials: C[m,n] = sum_s P[s][m*N+n] + bias[n]
__global__ __launch_bounds__(256)
void reduce_add_bias(int S, int total, int N,
                     const float* __restrict__ P,
                     const float* __restrict__ bias,
                     float* __restrict__ C)
{
    int idx = blockIdx.x * 256 + threadIdx.x;
    if (idx >= total) return;
    float acc = 0.f;
    for (int s = 0; s < S; s++) acc += P[(size_t)s * total + idx];
    C[idx] = acc + bias[idx % N];
}

// ---------------------------------------------------------------
// 3) Per-head t GEMM: t[h*64+b, e] = sum_d q[b, h*64+d] * Wk[h*64+d, e]
//    grid (etile=12, head=12), NN, K=64
// ---------------------------------------------------------------
__global__ __launch_bounds__(256)
void thead_gemm(const float* __restrict__ q,
                const float* __restrict__ Wk,   // in_proj_w + E*E
                float* __restrict__ T)
{
    __shared__ float As[64][65];   // [d][m]
    __shared__ float Bs[64][65];   // [d][e]
    const int e0 = blockIdx.x * 64;
    const int h  = blockIdx.y;
    const int tid = threadIdx.x;
    const int tx = tid & 15, ty = tid >> 4;

    #pragma unroll
    for (int i = tid; i < 4096; i += 256) {
        int m = i >> 6, d = i & 63;
        As[d][m] = q[(size_t)m * E_SZ + h*64 + d];
    }
    #pragma unroll
    for (int i = tid; i < 4096; i += 256) {
        int d = i >> 6, e = i & 63;
        Bs[d][e] = Wk[(size_t)(h*64 + d) * E_SZ + e0 + e];
    }
    __syncthreads();

    float acc[4][4] = {};
    #pragma unroll 16
    for (int d = 0; d < 64; d++) {
        float a[4], bb[4];
        #pragma unroll
        for (int i = 0; i < 4; i++) a[i]  = As[d][ty*4+i];
        #pragma unroll
        for (int j = 0; j < 4; j++) bb[j] = Bs[d][tx*4+j];
        #pragma unroll
        for (int i = 0; i < 4; i++)
            #pragma unroll
            for (int j = 0; j < 4; j++)
                acc[i][j] = fmaf(a[i], bb[j], acc[i][j]);
    }
    #pragma unroll
    for (int i = 0; i < 4; i++)
        #pragma unroll
        for (int j = 0; j < 4; j++)
            T[(size_t)(h*64 + ty*4+i) * E_SZ + e0 + tx*4+j] = acc[i][j];
}

// ---------------------------------------------------------------
// 4) Big 768x768x768 GEMMs, K-split x2 -> partials g_PB
// ---------------------------------------------------------------
__global__ __launch_bounds__(256)
void sgemm_nn_big_split(const float* __restrict__ A,
                        const float* __restrict__ B,
                        float* __restrict__ P)
{
    __shared__ float As[16][65];
    __shared__ float Bs[16][65];
    const int bn = blockIdx.x * 64;
    const int bm = blockIdx.y * 64;
    const int k0base = blockIdx.z * 384;
    const int tid = threadIdx.x;
    const int tx = tid & 15, ty = tid >> 4;

    float acc[4][4] = {};
    for (int k0 = k0base; k0 < k0base + 384; k0 += 16) {
        #pragma unroll
        for (int i = tid; i < 1024; i += 256) {
            int m = i >> 4, k = i & 15;
            As[k][m] = A[(size_t)(bm + m) * E_SZ + k0 + k];
        }
        #pragma unroll
        for (int i = tid; i < 1024; i += 256) {
            int k = i >> 6, n = i & 63;
            Bs[k][n] = B[(size_t)(k0 + k) * E_SZ + bn + n];
        }
        __syncthreads();
        #pragma unroll
        for (int kk = 0; kk < 16; kk++) {
            float a[4], bb[4];
            #pragma unroll
            for (int i = 0; i < 4; i++) a[i]  = As[kk][ty*4+i];
            #pragma unroll
            for (int j = 0; j < 4; j++) bb[j] = Bs[kk][tx*4+j];
            #pragma unroll
            for (int i = 0; i < 4; i++)
                #pragma unroll
                for (int j = 0; j < 4; j++)
                    acc[i][j] = fmaf(a[i], bb[j], acc[i][j]);
        }
        __syncthreads();
    }
    float* Pp = P + (size_t)blockIdx.z * E_SZ * E_SZ;
    #pragma unroll
    for (int i = 0; i < 4; i++)
        #pragma unroll
        for (int j = 0; j < 4; j++)
            Pp[(size_t)(bm + ty*4+i) * E_SZ + bn + tx*4+j] = acc[i][j];
}

__global__ __launch_bounds__(256)
void sgemm_nt_big_split(const float* __restrict__ A,
                        const float* __restrict__ B,
                        float* __restrict__ P)
{
    __shared__ float As[16][65];
    __shared__ float Bs[16][65];
    const int bn = blockIdx.x * 64;
    const int bm = blockIdx.y * 64;
    const int k0base = blockIdx.z * 384;
    const int tid = threadIdx.x;
    const int tx = tid & 15, ty = tid >> 4;

    float acc[4][4] = {};
    for (int k0 = k0base; k0 < k0base + 384; k0 += 16) {
        #pragma unroll
        for (int i = tid; i < 1024; i += 256) {
            int m = i >> 4, k = i & 15;
            As[k][m] = A[(size_t)(bm + m) * E_SZ + k0 + k];
        }
        #pragma unroll
        for (int i = tid; i < 1024; i += 256) {
            int n = i >> 4, k = i & 15;
            Bs[k][n] = B[(size_t)(bn + n) * E_SZ + k0 + k];
        }
        __syncthreads();
        #pragma unroll
        for (int kk = 0; kk < 16; kk++) {
            float a[4], bb[4];
            #pragma unroll
            for (int i = 0; i < 4; i++) a[i]  = As[kk][ty*4+i];
            #pragma unroll
            for (int j = 0; j < 4; j++) bb[j] = Bs[kk][tx*4+j];
            #pragma unroll
            for (int i = 0; i < 4; i++)
                #pragma unroll
                for (int j = 0; j < 4; j++)
                    acc[i][j] = fmaf(a[i], bb[j], acc[i][j]);
        }
        __syncthreads();
    }
    float* Pp = P + (size_t)blockIdx.z * E_SZ * E_SZ;
    #pragma unroll
    for (int i = 0; i < 4; i++)
        #pragma unroll
        for (int j = 0; j < 4; j++)
            Pp[(size_t)(bm + ty*4+i) * E_SZ + bn + tx*4+j] = acc[i][j];
}

// C[idx] = P[0][idx] + P[1][idx] (+ bias[n])
__global__ __launch_bounds__(256)
void reduce2_bias(const float* __restrict__ P,
                  const float* __restrict__ bias,
                  float* __restrict__ C)
{
    int idx = blockIdx.x * 256 + threadIdx.x;
    if (idx >= E_SZ * E_SZ) return;
    float v = P[idx] + P[E_SZ * E_SZ + idx];
    if (bias) v += bias[idx % E_SZ];
    C[idx] = v;
}

// ---------------------------------------------------------------
// 5) Fused attention: scores + softmax + weighted S. Block per batch.
// ---------------------------------------------------------------
__global__ __launch_bounds__(512)
void attn_fuse_kernel(const float* __restrict__ QH,
                      const float* __restrict__ S,
                      float* __restrict__ WS)
{
    extern __shared__ float sm[];
    float* Ssm = sm;                       // 32*768
    float* sc  = sm + NB * E_SZ;           // 12*32
    float* at  = sc + NHEAD * NB;          // 12*32

    const int b = blockIdx.x;
    const int t = threadIdx.x;

    // stage 1: load S[b] tile into smem
    {
        const float4* src = (const float4*)(S + (size_t)b * NB * E_SZ);
        float4* dst = (float4*)Ssm;
        for (int i = t; i < NB * E_SZ / 4; i += 512) dst[i] = src[i];
    }
    __syncthreads();

    const int w = t >> 5, lane = t & 31;

    // stage 2: 384 dot products (h,p)
    for (int j = w; j < NHEAD * NB; j += 16) {
        int h = j >> 5, p = j & 31;
        const float* qr = QH + (size_t)(h*64 + b) * E_SZ;
        const float* sr = Ssm + p * E_SZ;
        float acc = 0.f;
        for (int c = lane; c < E_SZ; c += 32)
            acc = fmaf(qr[c], sr[c], acc);
        #pragma unroll
        for (int o = 16; o; o >>= 1) acc += __shfl_xor_sync(0xffffffffu, acc, o);
        if (lane == 0) sc[j] = acc * 0.125f;
    }
    __syncthreads();

    // stage 3: softmax over p per head (warp w < 12 handles head w)
    if (w < NHEAD) {
        float s = sc[w*32 + lane];
        float m = s;
        #pragma unroll
        for (int o = 16; o; o >>= 1) m = fmaxf(m, __shfl_xor_sync(0xffffffffu, m, o));
        float e = __expf(s - m);
        float sum = e;
        #pragma unroll
        for (int o = 16; o; o >>= 1) sum += __shfl_xor_sync(0xffffffffu, sum, o);
        at[w*32 + lane] = e / sum;
    }
    __syncthreads();

    // stage 4: ws[h*64+b, c] = sum_p attn[h,p] * S[b,p,c]
    for (int idx = t; idx < NHEAD * E_SZ; idx += 512) {
        int h = idx / E_SZ, c = idx - h * E_SZ;
        float acc = 0.f;
        #pragma unroll
        for (int p = 0; p < NB; p++)
            acc = fmaf(at[h*32 + p], Ssm[p * E_SZ + c], acc);
        WS[(size_t)(h*64 + b) * E_SZ + c] = acc;
    }
}

// ---------------------------------------------------------------
// 6) Per-head ctx GEMM partials: C_h[b,d] = sum_o U[h*64+b,o]*Wv[h*64+d,o]
//    grid (head=12, ksplit=8), chunk 96
// ---------------------------------------------------------------
__global__ __launch_bounds__(256)
void ctx_perhead_split(const float* __restrict__ U,
                       const float* __restrict__ in_proj_w,
                       float* __restrict__ P2)
{
    __shared__ float As[16][65];
    __shared__ float Bs[16][65];
    const int h = blockIdx.x, s = blockIdx.y;
    const float* A  = U + (size_t)h * 64 * E_SZ;
    const float* Bp = in_proj_w + (size_t)(2*E_SZ + h*64) * E_SZ;
    const int k0base = s * 96;
    const int tid = threadIdx.x;
    const int tx = tid & 15, ty = tid >> 4;

    float acc[4][4] = {};
    for (int k0 = k0base; k0 < k0base + 96; k0 += 16) {
        #pragma unroll
        for (int i = tid; i < 1024; i += 256) {
            int m = i >> 4, k = i & 15;
            As[k][m] = A[(size_t)m * E_SZ + k0 + k];
        }
        #pragma unroll
        for (int i = tid; i < 1024; i += 256) {
            int n = i >> 4, k = i & 15;
            Bs[k][n] = Bp[(size_t)n * E_SZ + k0 + k];
        }
        __syncthreads();
        #pragma unroll
        for (int kk = 0; kk < 16; kk++) {
            float a[4], bb[4];
            #pragma unroll
            for (int i = 0; i < 4; i++) a[i]  = As[kk][ty*4+i];
            #pragma unroll
            for (int j = 0; j < 4; j++) bb[j] = Bs[kk][tx*4+j];
            #pragma unroll
            for (int i = 0; i < 4; i++)
                #pragma unroll
                for (int j = 0; j < 4; j++)
                    acc[i][j] = fmaf(a[i], bb[j], acc[i][j]);
        }
        __syncthreads();
    }
    float* Pp = P2 + (size_t)(h*8 + s) * 4096;
    #pragma unroll
    for (int i = 0; i < 4; i++)
        #pragma unroll
        for (int j = 0; j < 4; j++)
            Pp[(ty*4+i) * 64 + tx*4+j] = acc[i][j];
}

// ctx[b, h*64+d] = sum_s P2[h][s][b,d] + bv[h*64+d]
__global__ __launch_bounds__(256)
void reduce_ctx(const float* __restrict__ P2,
                const float* __restrict__ in_proj_b,
                float* __restrict__ ctx)
{
    int idx = blockIdx.x * 256 + threadIdx.x;
    if (idx >= B_SZ * E_SZ) return;
    int b = idx / E_SZ, r = idx - b * E_SZ;
    int h = r >> 6, d = r & 63;
    float acc = 0.f;
    #pragma unroll
    for (int s = 0; s < 8; s++)
        acc += P2[(size_t)(h*8 + s) * 4096 + b * 64 + d];
    ctx[idx] = acc + in_proj_b[2*E_SZ + r];
}

// ---------------------------------------------------------------
// 7) Broadcast * confidence
// ---------------------------------------------------------------
__global__ __launch_bounds__(192)
void broadcast_kernel(const float* __restrict__ ao,
                      const float* __restrict__ conf,
                      float* __restrict__ out)
{
    const int n = blockIdx.x;
    const int b = blockIdx.y;
    const float cf = conf[b];
    const float4* src = (const float4*)(ao + (size_t)b * E_SZ);
    float4* dst = (float4*)(out + ((size_t)b * FULLN + n) * E_SZ);
    float4 v = src[threadIdx.x];
    v.x *= cf; v.y *= cf; v.z *= cf; v.w *= cf;
    dst[threadIdx.x] = v;
}

// ---------------------------------------------------------------
extern "C" void kernel_launch(void* const* d_in, const int* in_sizes, int n_in,
                              void* d_out, int out_size)
{
    const float* x           = (const float*)d_in[0];
    const float* bio_embed   = (const float*)d_in[1];
    const float* base_coords = (const float*)d_in[2];
    const float* offsets     = (const float*)d_in[3];
    const float* confidence  = (const float*)d_in[4];
    const float* sample_w    = (const float*)d_in[5];
    const float* sample_b    = (const float*)d_in[6];
    const float* in_proj_w   = (const float*)d_in[7];
    const float* in_proj_b   = (const float*)d_in[8];
    const float* out_proj_w  = (const float*)d_in[9];
    const float* out_proj_b  = (const float*)d_in[10];
    float* out = (float*)d_out;

    float *S, *q, *T, *QH, *WS, *U, *CTX, *AO, *P1, *P2, *PB;
    cudaGetSymbolAddress((void**)&S,   g_S);
    cudaGetSymbolAddress((void**)&q,   g_q);
    cudaGetSymbolAddress((void**)&T,   g_T);
    cudaGetSymbolAddress((void**)&QH,  g_QH);
    cudaGetSymbolAddress((void**)&WS,  g_WS);
    cudaGetSymbolAddress((void**)&U,   g_U);
    cudaGetSymbolAddress((void**)&CTX, g_CTX);
    cudaGetSymbolAddress((void**)&AO,  g_AO);
    cudaGetSymbolAddress((void**)&P1,  g_P1);
    cudaGetSymbolAddress((void**)&P2,  g_P2);
    cudaGetSymbolAddress((void**)&PB,  g_PB);

    const int attn_smem = (NB * E_SZ + 2 * NHEAD * NB) * sizeof(float);  // ~101.4 KB
    cudaFuncSetAttribute(attn_fuse_kernel,
                         cudaFuncAttributeMaxDynamicSharedMemorySize, attn_smem);

    // 1) trilinear gather -> S (2048 x 768)
    gather_kernel<<<NP, 192>>>(x, base_coords, offsets, S);

    // 2) q = bio @ Wq^T + bq  (64x768x768), K-split x12
    sgemm_nt64_split<<<dim3(12, 12), 256>>>(E_SZ, 64, bio_embed, in_proj_w, P1);
    reduce_add_bias<<<(B_SZ*E_SZ + 255)/256, 256>>>(12, B_SZ*E_SZ, E_SZ, P1, in_proj_b, q);

    // 3) t[h*64+b,:] = q[b, h-slice] @ Wk[h-slice,:]  (per-head NN, K=64)
    thead_gemm<<<dim3(12, 12), 256>>>(q, in_proj_w + (size_t)E_SZ * E_SZ, T);

    // 4) QH = T @ Ws   (768x768x768 NN, K-split x2)
    sgemm_nn_big_split<<<dim3(12, 12, 2), 256>>>(T, sample_w, PB);
    reduce2_bias<<<(E_SZ*E_SZ + 255)/256, 256>>>(PB, nullptr, QH);

    // 5) fused scores + softmax + weighted-S  -> WS
    attn_fuse_kernel<<<B_SZ, 512, attn_smem>>>(QH, S, WS);

    // 6) U = WS @ Ws^T + bs   (768x768x768 NT, K-split x2)
    sgemm_nt_big_split<<<dim3(12, 12, 2), 256>>>(WS, sample_w, PB);
    reduce2_bias<<<(E_SZ*E_SZ + 255)/256, 256>>>(PB, sample_b, U);

    // 7) ctx[b, h*64+d] = U[h*64+b,:] . Wv[h*64+d,:] + bv
    ctx_perhead_split<<<dim3(12, 8), 256>>>(U, in_proj_w, P2);
    reduce_ctx<<<(B_SZ*E_SZ + 255)/256, 256>>>(P2, in_proj_b, CTX);

    // 8) attn_out = ctx @ Wo^T + bo  (64x768x768), K-split x12
    sgemm_nt64_split<<<dim3(12, 12), 256>>>(E_SZ, 64, CTX, out_proj_w, P1);
    reduce_add_bias<<<(B_SZ*E_SZ + 255)/256, 256>>>(12, B_SZ*E_SZ, E_SZ, P1, out_proj_b, AO);

    // 9) broadcast * confidence
    broadcast_kernel<<<dim3(FULLN, B_SZ), 192>>>(AO, confidence, out);
}

// round 4
// speedup vs baseline: 4.5740x; 1.3478x over previous
#include <cuda_runtime.h>
#include <cuda_bf16.h>
#include <math.h>
#include <stdint.h>

#define B_SZ   64
#define FULLN  513
#define E_SZ   768
#define NB     32
#define GRIDSZ 8
#define NHEAD  12
#define HDIM   64
#define NP     (B_SZ * NB)      // 2048

// ---------------- scratch (device globals) ----------------
__device__ float g_S  [NP * E_SZ];        // trilinear samples (2048 x 768)
__device__ float g_q  [B_SZ * E_SZ];      // q per batch (64 x 768)
__device__ float g_T  [E_SZ * E_SZ];      // t rows h*64+b
__device__ float g_QH [E_SZ * E_SZ];      // qh' rows h*64+b
__device__ float g_WS [E_SZ * E_SZ];      // attn-weighted S, rows h*64+b
__device__ float g_U  [E_SZ * E_SZ];      // ws @ Ws^T + bs
__device__ float g_CTX[B_SZ * E_SZ];
__device__ float g_AO [B_SZ * E_SZ];
__device__ float g_P1 [12 * B_SZ * E_SZ];     // small-NT partials
__device__ float g_P2 [12 * 8 * 64 * 64];     // per-head ctx partials
__device__ float g_WsT[E_SZ * E_SZ];          // sample_w transposed

// ================= SIMT tensor-core helpers (sm_80+ PTX, compiles for compute_103) =================
__device__ __forceinline__ uint32_t smem_u32(const void* p) {
    uint32_t a;
    asm("{ .reg .u64 t; cvta.to.shared.u64 t, %1; cvt.u32.u64 %0, t; }" : "=r"(a) : "l"(p));
    return a;
}
__device__ __forceinline__ void ldsm4(uint32_t* r, uint32_t addr) {
    asm volatile("ldmatrix.sync.aligned.m8n8.x4.shared.b16 {%0,%1,%2,%3}, [%4];"
        : "=r"(r[0]), "=r"(r[1]), "=r"(r[2]), "=r"(r[3]) : "r"(addr));
}
__device__ __forceinline__ void mma16816(float* d, const uint32_t* a, const uint32_t* b) {
    asm volatile("mma.sync.aligned.m16n8k16.row.col.f32.bf16.bf16.f32 "
        "{%0,%1,%2,%3}, {%4,%5,%6,%7}, {%8,%9}, {%0,%1,%2,%3};"
        : "+f"(d[0]), "+f"(d[1]), "+f"(d[2]), "+f"(d[3])
        : "r"(a[0]), "r"(a[1]), "r"(a[2]), "r"(a[3]), "r"(b[0]), "r"(b[1]));
}

// pack float4 -> two uint32 of bf16x2 (hi) and two uint32 (lo residual)
__device__ __forceinline__ void cvt_hl(float4 v, uint2& hi, uint2& lo) {
    __nv_bfloat16 h0 = __float2bfloat16(v.x), h1 = __float2bfloat16(v.y);
    __nv_bfloat16 h2 = __float2bfloat16(v.z), h3 = __float2bfloat16(v.w);
    __nv_bfloat16 l0 = __float2bfloat16(v.x - __bfloat162float(h0));
    __nv_bfloat16 l1 = __float2bfloat16(v.y - __bfloat162float(h1));
    __nv_bfloat16 l2 = __float2bfloat16(v.z - __bfloat162float(h2));
    __nv_bfloat16 l3 = __float2bfloat16(v.w - __bfloat162float(h3));
    __nv_bfloat162 hp0 = __halves2bfloat162(h0, h1), hp1 = __halves2bfloat162(h2, h3);
    __nv_bfloat162 lp0 = __halves2bfloat162(l0, l1), lp1 = __halves2bfloat162(l2, l3);
    hi = make_uint2(*(uint32_t*)&hp0, *(uint32_t*)&hp1);
    lo = make_uint2(*(uint32_t*)&lp0, *(uint32_t*)&lp1);
}

// ---------------------------------------------------------------
// HMMA NT GEMM: C[m,n] = sum_k A[m,k]*B[n,k] (+bias[n])
// M=N=K=768. CTA 64x64, 4 warps (warp 32x32), BK=64, bf16 hi/lo split.
// smem pitch 144 B (64 bf16 + 8 pad) -> conflict-free ldmatrix.
// ---------------------------------------------------------------
#define PITCH 144
#define A_H_OFF 0
#define A_L_OFF 9216
#define B_H_OFF 18432
#define B_L_OFF 27648

__global__ __launch_bounds__(128)
void hmma_gemm_nt(const float* __restrict__ A,
                  const float* __restrict__ B,
                  const float* __restrict__ bias,
                  float* __restrict__ C)
{
    __shared__ __align__(16) char sm[36864];
    const int tid  = threadIdx.x;
    const int wid  = tid >> 5, lane = tid & 31;
    const int bm   = blockIdx.y * 64, bn = blockIdx.x * 64;
    const int wm   = (wid & 1) * 32, wn = (wid >> 1) * 32;

    const uint32_t sb = smem_u32(sm);

    float acc[2][4][4];
    #pragma unroll
    for (int mi = 0; mi < 2; mi++)
        #pragma unroll
        for (int ni = 0; ni < 4; ni++)
            #pragma unroll
            for (int r = 0; r < 4; r++) acc[mi][ni][r] = 0.f;

    for (int k0 = 0; k0 < E_SZ; k0 += 64) {
        // ---- load + convert A (64x64) and B (64x64) tiles ----
        #pragma unroll
        for (int j = 0; j < 8; j++) {
            int fid = tid + j * 128;          // 0..1023
            int row = fid >> 4, c4 = fid & 15;
            uint2 hi, lo;
            float4 va = *(const float4*)(A + (size_t)(bm + row) * E_SZ + k0 + c4 * 4);
            cvt_hl(va, hi, lo);
            *(uint2*)(sm + A_H_OFF + row * PITCH + c4 * 8) = hi;
            *(uint2*)(sm + A_L_OFF + row * PITCH + c4 * 8) = lo;
            float4 vb = *(const float4*)(B + (size_t)(bn + row) * E_SZ + k0 + c4 * 4);
            cvt_hl(vb, hi, lo);
            *(uint2*)(sm + B_H_OFF + row * PITCH + c4 * 8) = hi;
            *(uint2*)(sm + B_L_OFF + row * PITCH + c4 * 8) = lo;
        }
        __syncthreads();

        #pragma unroll
        for (int ks = 0; ks < 4; ks++) {
            uint32_t a_h[2][4], a_l[2][4], b_h[4][2], b_l[4][2];
            // A fragments: rows wm+mi*16 + (lane&15), col byte = ks*32 + (lane>>4)*16
            #pragma unroll
            for (int mi = 0; mi < 2; mi++) {
                uint32_t r  = wm + mi * 16 + (lane & 15);
                uint32_t cb = ks * 32 + ((lane >> 4) << 4);
                ldsm4(a_h[mi], sb + A_H_OFF + r * PITCH + cb);
                ldsm4(a_l[mi], sb + A_L_OFF + r * PITCH + cb);
            }
            // B fragments: n rows, quads (n0-7,k0-7),(n0-7,k8-15),(n8-15,k0-7),(n8-15,k8-15)
            #pragma unroll
            for (int g = 0; g < 2; g++) {
                uint32_t n  = wn + g * 16 + (lane & 7) + (((lane >> 4) & 1) << 3);
                uint32_t cb = ks * 32 + (((lane >> 3) & 1) << 4);
                uint32_t t[4];
                ldsm4(t, sb + B_H_OFF + n * PITCH + cb);
                b_h[g*2][0] = t[0]; b_h[g*2][1] = t[1];
                b_h[g*2+1][0] = t[2]; b_h[g*2+1][1] = t[3];
                ldsm4(t, sb + B_L_OFF + n * PITCH + cb);
                b_l[g*2][0] = t[0]; b_l[g*2][1] = t[1];
                b_l[g*2+1][0] = t[2]; b_l[g*2+1][1] = t[3];
            }
            #pragma unroll
            for (int mi = 0; mi < 2; mi++)
                #pragma unroll
                for (int ni = 0; ni < 4; ni++) {
                    mma16816(acc[mi][ni], a_h[mi], b_h[ni]);
                    mma16816(acc[mi][ni], a_h[mi], b_l[ni]);
                    mma16816(acc[mi][ni], a_l[mi], b_h[ni]);
                }
        }
        __syncthreads();
    }

    // ---- epilogue ----
    #pragma unroll
    for (int mi = 0; mi < 2; mi++) {
        int r0 = bm + wm + mi * 16 + (lane >> 2);
        #pragma unroll
        for (int ni = 0; ni < 4; ni++) {
            int c0 = bn + wn + ni * 8 + (lane & 3) * 2;
            float bb0 = bias ? bias[c0] : 0.f;
            float bb1 = bias ? bias[c0 + 1] : 0.f;
            *(float2*)(C + (size_t)r0 * E_SZ + c0) =
                make_float2(acc[mi][ni][0] + bb0, acc[mi][ni][1] + bb1);
            *(float2*)(C + (size_t)(r0 + 8) * E_SZ + c0) =
                make_float2(acc[mi][ni][2] + bb0, acc[mi][ni][3] + bb1);
        }
    }
}

// ---------------------------------------------------------------
// transpose 768x768 fp32
// ---------------------------------------------------------------
__global__ __launch_bounds__(256)
void transpose768(const float* __restrict__ A, float* __restrict__ At)
{
    __shared__ float t[32][33];
    const int bx = blockIdx.x * 32, by = blockIdx.y * 32;
    #pragma unroll
    for (int i = 0; i < 32; i += 8)
        t[threadIdx.y + i][threadIdx.x] = A[(size_t)(by + threadIdx.y + i) * E_SZ + bx + threadIdx.x];
    __syncthreads();
    #pragma unroll
    for (int i = 0; i < 32; i += 8)
        At[(size_t)(bx + threadIdx.y + i) * E_SZ + by + threadIdx.x] = t[threadIdx.x][threadIdx.y + i];
}

// ---------------------------------------------------------------
// 1) Trilinear border sampling
// ---------------------------------------------------------------
__global__ __launch_bounds__(192)
void gather_kernel(const float* __restrict__ x,
                   const float* __restrict__ bc,
                   const float* __restrict__ off,
                   float* __restrict__ S)
{
    const int bp = blockIdx.x;
    const int b  = bp >> 5;
    const int p  = bp & 31;

    float cx = fminf(fmaxf(bc[p*3+0] + off[bp*3+0], -1.f), 1.f);
    float cy = fminf(fmaxf(bc[p*3+1] + off[bp*3+1], -1.f), 1.f);
    float cz = fminf(fmaxf(bc[p*3+2] + off[bp*3+2], -1.f), 1.f);

    float ix = (cx + 1.0f) * 0.5f * (GRIDSZ - 1);
    float iy = (cy + 1.0f) * 0.5f * (GRIDSZ - 1);
    float iz = (cz + 1.0f) * 0.5f * (GRIDSZ - 1);

    float fx = floorf(ix), fy = floorf(iy), fz = floorf(iz);
    float wx = ix - fx, wy = iy - fy, wz = iz - fz;

    int x0 = min(max((int)fx, 0), GRIDSZ-1);
    int y0 = min(max((int)fy, 0), GRIDSZ-1);
    int z0 = min(max((int)fz, 0), GRIDSZ-1);
    int x1 = min(x0 + 1, GRIDSZ-1);
    int y1 = min(y0 + 1, GRIDSZ-1);
    int z1 = min(z0 + 1, GRIDSZ-1);

    const float* xb = x + ((size_t)b * FULLN + 1) * E_SZ;

    int idx[8];
    idx[0] = (((z0*GRIDSZ)+y0)*GRIDSZ + x0) * E_SZ;
    idx[1] = (((z0*GRIDSZ)+y0)*GRIDSZ + x1) * E_SZ;
    idx[2] = (((z0*GRIDSZ)+y1)*GRIDSZ + x0) * E_SZ;
    idx[3] = (((z0*GRIDSZ)+y1)*GRIDSZ + x1) * E_SZ;
    idx[4] = (((z1*GRIDSZ)+y0)*GRIDSZ + x0) * E_SZ;
    idx[5] = (((z1*GRIDSZ)+y0)*GRIDSZ + x1) * E_SZ;
    idx[6] = (((z1*GRIDSZ)+y1)*GRIDSZ + x0) * E_SZ;
    idx[7] = (((z1*GRIDSZ)+y1)*GRIDSZ + x1) * E_SZ;

    float w[8];
    w[0] = (1-wz)*(1-wy)*(1-wx);
    w[1] = (1-wz)*(1-wy)*wx;
    w[2] = (1-wz)*wy*(1-wx);
    w[3] = (1-wz)*wy*wx;
    w[4] = wz*(1-wy)*(1-wx);
    w[5] = wz*(1-wy)*wx;
    w[6] = wz*wy*(1-wx);
    w[7] = wz*wy*wx;

    float4* out = (float4*)(S + (size_t)bp * E_SZ);
    const int c = threadIdx.x;
    float4 acc = make_float4(0.f,0.f,0.f,0.f);
    #pragma unroll
    for (int i = 0; i < 8; i++) {
        float4 v = ((const float4*)(xb + idx[i]))[c];
        acc.x = fmaf(w[i], v.x, acc.x);
        acc.y = fmaf(w[i], v.y, acc.y);
        acc.z = fmaf(w[i], v.z, acc.z);
        acc.w = fmaf(w[i], v.w, acc.w);
    }
    out[c] = acc;
}

// ---------------------------------------------------------------
// 2) Small-M NT GEMM with K-split (M=64)
// ---------------------------------------------------------------
__global__ __launch_bounds__(256)
void sgemm_nt64_split(int N, int kchunk,
                      const float* __restrict__ A,
                      const float* __restrict__ B,
                      float* __restrict__ P)
{
    __shared__ float As[16][65];
    __shared__ float Bs[16][65];
    const int bn = blockIdx.x * 64;
    const int k0base = blockIdx.y * kchunk;
    const int tid = threadIdx.x;
    const int tx = tid & 15, ty = tid >> 4;

    float acc[4][4] = {};
    for (int k0 = k0base; k0 < k0base + kchunk; k0 += 16) {
        #pragma unroll
        for (int i = tid; i < 1024; i += 256) {
            int m = i >> 4, k = i & 15;
            As[k][m] = A[(size_t)m * E_SZ + k0 + k];
        }
        #pragma unroll
        for (int i = tid; i < 1024; i += 256) {
            int n = i >> 4, k = i & 15;
            Bs[k][n] = B[(size_t)(bn + n) * E_SZ + k0 + k];
        }
        __syncthreads();
        #pragma unroll
        for (int kk = 0; kk < 16; kk++) {
            float a[4], bb[4];
            #pragma unroll
            for (int i = 0; i < 4; i++) a[i]  = As[kk][ty*4+i];
            #pragma unroll
            for (int j = 0; j < 4; j++) bb[j] = Bs[kk][tx*4+j];
            #pragma unroll
            for (int i = 0; i < 4; i++)
                #pragma unroll
                for (int j = 0; j < 4; j++)
                    acc[i][j] = fmaf(a[i], bb[j], acc[i][j]);
        }
        __syncthreads();
    }
    float* Pp = P + (size_t)blockIdx.y * 64 * N;
    #pragma unroll
    for (int i = 0; i < 4; i++)
        #pragma unroll
        for (int j = 0; j < 4; j++)
            Pp[(size_t)(ty*4+i) * N + bn + tx*4+j] = acc[i][j];
}

__global__ __launch_bounds__(256)
void reduce_add_bias(int S, int total, int N,
                     const float* __restrict__ P,
                     const float* __restrict__ bias,
                     float* __restrict__ C)
{
    int idx = blockIdx.x * 256 + threadIdx.x;
    if (idx >= total) return;
    float acc = 0.f;
    for (int s = 0; s < S; s++) acc += P[(size_t)s * total + idx];
    C[idx] = acc + bias[idx % N];
}

// ---------------------------------------------------------------
// 3) Per-head t GEMM: t[h*64+b, e] = sum_d q[b, h*64+d]*Wk[h*64+d, e]
// ---------------------------------------------------------------
__global__ __launch_bounds__(256)
void thead_gemm(const float* __restrict__ q,
                const float* __restrict__ Wk,
                float* __restrict__ T)
{
    __shared__ float As[64][65];
    __shared__ float Bs[64][65];
    const int e0 = blockIdx.x * 64;
    const int h  = blockIdx.y;
    const int tid = threadIdx.x;
    const int tx = tid & 15, ty = tid >> 4;

    #pragma unroll
    for (int i = tid; i < 4096; i += 256) {
        int m = i >> 6, d = i & 63;
        As[d][m] = q[(size_t)m * E_SZ + h*64 + d];
    }
    #pragma unroll
    for (int i = tid; i < 4096; i += 256) {
        int d = i >> 6, e = i & 63;
        Bs[d][e] = Wk[(size_t)(h*64 + d) * E_SZ + e0 + e];
    }
    __syncthreads();

    float acc[4][4] = {};
    #pragma unroll 16
    for (int d = 0; d < 64; d++) {
        float a[4], bb[4];
        #pragma unroll
        for (int i = 0; i < 4; i++) a[i]  = As[d][ty*4+i];
        #pragma unroll
        for (int j = 0; j < 4; j++) bb[j] = Bs[d][tx*4+j];
        #pragma unroll
        for (int i = 0; i < 4; i++)
            #pragma unroll
            for (int j = 0; j < 4; j++)
                acc[i][j] = fmaf(a[i], bb[j], acc[i][j]);
    }
    #pragma unroll
    for (int i = 0; i < 4; i++)
        #pragma unroll
        for (int j = 0; j < 4; j++)
            T[(size_t)(h*64 + ty*4+i) * E_SZ + e0 + tx*4+j] = acc[i][j];
}

// ---------------------------------------------------------------
// 5) Fused attention: scores + softmax + weighted S
// ---------------------------------------------------------------
__global__ __launch_bounds__(512)
void attn_fuse_kernel(const float* __restrict__ QH,
                      const float* __restrict__ S,
                      float* __restrict__ WS)
{
    extern __shared__ float smf[];
    float* Ssm = smf;
    float* sc  = smf + NB * E_SZ;
    float* at  = sc + NHEAD * NB;

    const int b = blockIdx.x;
    const int t = threadIdx.x;

    {
        const float4* src = (const float4*)(S + (size_t)b * NB * E_SZ);
        float4* dst = (float4*)Ssm;
        for (int i = t; i < NB * E_SZ / 4; i += 512) dst[i] = src[i];
    }
    __syncthreads();

    const int w = t >> 5, lane = t & 31;

    for (int j = w; j < NHEAD * NB; j += 16) {
        int h = j >> 5, p = j & 31;
        const float* qr = QH + (size_t)(h*64 + b) * E_SZ;
        const float* sr = Ssm + p * E_SZ;
        float acc = 0.f;
        for (int c = lane; c < E_SZ; c += 32)
            acc = fmaf(qr[c], sr[c], acc);
        #pragma unroll
        for (int o = 16; o; o >>= 1) acc += __shfl_xor_sync(0xffffffffu, acc, o);
        if (lane == 0) sc[j] = acc * 0.125f;
    }
    __syncthreads();

    if (w < NHEAD) {
        float s = sc[w*32 + lane];
        float m = s;
        #pragma unroll
        for (int o = 16; o; o >>= 1) m = fmaxf(m, __shfl_xor_sync(0xffffffffu, m, o));
        float e = __expf(s - m);
        float sum = e;
        #pragma unroll
        for (int o = 16; o; o >>= 1) sum += __shfl_xor_sync(0xffffffffu, sum, o);
        at[w*32 + lane] = e / sum;
    }
    __syncthreads();

    for (int idx = t; idx < NHEAD * E_SZ; idx += 512) {
        int h = idx / E_SZ, c = idx - h * E_SZ;
        float acc = 0.f;
        #pragma unroll
        for (int p = 0; p < NB; p++)
            acc = fmaf(at[h*32 + p], Ssm[p * E_SZ + c], acc);
        WS[(size_t)(h*64 + b) * E_SZ + c] = acc;
    }
}

// ---------------------------------------------------------------
// 6) Per-head ctx GEMM partials
// ---------------------------------------------------------------
__global__ __launch_bounds__(256)
void ctx_perhead_split(const float* __restrict__ U,
                       const float* __restrict__ in_proj_w,
                       float* __restrict__ P2)
{
    __shared__ float As[16][65];
    __shared__ float Bs[16][65];
    const int h = blockIdx.x, s = blockIdx.y;
    const float* A  = U + (size_t)h * 64 * E_SZ;
    const float* Bp = in_proj_w + (size_t)(2*E_SZ + h*64) * E_SZ;
    const int k0base = s * 96;
    const int tid = threadIdx.x;
    const int tx = tid & 15, ty = tid >> 4;

    float acc[4][4] = {};
    for (int k0 = k0base; k0 < k0base + 96; k0 += 16) {
        #pragma unroll
        for (int i = tid; i < 1024; i += 256) {
            int m = i >> 4, k = i & 15;
            As[k][m] = A[(size_t)m * E_SZ + k0 + k];
        }
        #pragma unroll
        for (int i = tid; i < 1024; i += 256) {
            int n = i >> 4, k = i & 15;
            Bs[k][n] = Bp[(size_t)n * E_SZ + k0 + k];
        }
        __syncthreads();
        #pragma unroll
        for (int kk = 0; kk < 16; kk++) {
            float a[4], bb[4];
            #pragma unroll
            for (int i = 0; i < 4; i++) a[i]  = As[kk][ty*4+i];
            #pragma unroll
            for (int j = 0; j < 4; j++) bb[j] = Bs[kk][tx*4+j];
            #pragma unroll
            for (int i = 0; i < 4; i++)
                #pragma unroll
                for (int j = 0; j < 4; j++)
                    acc[i][j] = fmaf(a[i], bb[j], acc[i][j]);
        }
        __syncthreads();
    }
    float* Pp = P2 + (size_t)(h*8 + s) * 4096;
    #pragma unroll
    for (int i = 0; i < 4; i++)
        #pragma unroll
        for (int j = 0; j < 4; j++)
            Pp[(ty*4+i) * 64 + tx*4+j] = acc[i][j];
}

__global__ __launch_bounds__(256)
void reduce_ctx(const float* __restrict__ P2,
                const float* __restrict__ in_proj_b,
                float* __restrict__ ctx)
{
    int idx = blockIdx.x * 256 + threadIdx.x;
    if (idx >= B_SZ * E_SZ) return;
    int b = idx / E_SZ, r = idx - b * E_SZ;
    int h = r >> 6, d = r & 63;
    float acc = 0.f;
    #pragma unroll
    for (int s = 0; s < 8; s++)
        acc += P2[(size_t)(h*8 + s) * 4096 + b * 64 + d];
    ctx[idx] = acc + in_proj_b[2*E_SZ + r];
}

// ---------------------------------------------------------------
// 7) Broadcast * confidence
// ---------------------------------------------------------------
__global__ __launch_bounds__(192)
void broadcast_kernel(const float* __restrict__ ao,
                      const float* __restrict__ conf,
                      float* __restrict__ out)
{
    const int n = blockIdx.x;
    const int b = blockIdx.y;
    const float cf = conf[b];
    const float4* src = (const float4*)(ao + (size_t)b * E_SZ);
    float4* dst = (float4*)(out + ((size_t)b * FULLN + n) * E_SZ);
    float4 v = src[threadIdx.x];
    v.x *= cf; v.y *= cf; v.z *= cf; v.w *= cf;
    dst[threadIdx.x] = v;
}

// ---------------------------------------------------------------
extern "C" void kernel_launch(void* const* d_in, const int* in_sizes, int n_in,
                              void* d_out, int out_size)
{
    const float* x           = (const float*)d_in[0];
    const float* bio_embed   = (const float*)d_in[1];
    const float* base_coords = (const float*)d_in[2];
    const float* offsets     = (const float*)d_in[3];
    const float* confidence  = (const float*)d_in[4];
    const float* sample_w    = (const float*)d_in[5];
    const float* sample_b    = (const float*)d_in[6];
    const float* in_proj_w   = (const float*)d_in[7];
    const float* in_proj_b   = (const float*)d_in[8];
    const float* out_proj_w  = (const float*)d_in[9];
    const float* out_proj_b  = (const float*)d_in[10];
    float* out = (float*)d_out;

    float *S, *q, *T, *QH, *WS, *U, *CTX, *AO, *P1, *P2, *WsT;
    cudaGetSymbolAddress((void**)&S,   g_S);
    cudaGetSymbolAddress((void**)&q,   g_q);
    cudaGetSymbolAddress((void**)&T,   g_T);
    cudaGetSymbolAddress((void**)&QH,  g_QH);
    cudaGetSymbolAddress((void**)&WS,  g_WS);
    cudaGetSymbolAddress((void**)&U,   g_U);
    cudaGetSymbolAddress((void**)&CTX, g_CTX);
    cudaGetSymbolAddress((void**)&AO,  g_AO);
    cudaGetSymbolAddress((void**)&P1,  g_P1);
    cudaGetSymbolAddress((void**)&P2,  g_P2);
    cudaGetSymbolAddress((void**)&WsT, g_WsT);

    const int attn_smem = (NB * E_SZ + 2 * NHEAD * NB) * sizeof(float);
    cudaFuncSetAttribute(attn_fuse_kernel,
                         cudaFuncAttributeMaxDynamicSharedMemorySize, attn_smem);

    // 0) Ws^T (weight-only, no deps)
    transpose768<<<dim3(24, 24), dim3(32, 8)>>>(sample_w, WsT);

    // 1) trilinear gather -> S
    gather_kernel<<<NP, 192>>>(x, base_coords, offsets, S);

    // 2) q = bio @ Wq^T + bq
    sgemm_nt64_split<<<dim3(12, 12), 256>>>(E_SZ, 64, bio_embed, in_proj_w, P1);
    reduce_add_bias<<<(B_SZ*E_SZ + 255)/256, 256>>>(12, B_SZ*E_SZ, E_SZ, P1, in_proj_b, q);

    // 3) T[h*64+b,:] = q_h @ Wk_h
    thead_gemm<<<dim3(12, 12), 256>>>(q, in_proj_w + (size_t)E_SZ * E_SZ, T);

    // 4) QH = T @ Ws  (NT against WsT) -- tensor cores
    hmma_gemm_nt<<<dim3(12, 12), 128>>>(T, WsT, nullptr, QH);

    // 5) fused scores + softmax + weighted-S
    attn_fuse_kernel<<<B_SZ, 512, attn_smem>>>(QH, S, WS);

    // 6) U = WS @ Ws^T + bs -- tensor cores
    hmma_gemm_nt<<<dim3(12, 12), 128>>>(WS, sample_w, sample_b, U);

    // 7) ctx
    ctx_perhead_split<<<dim3(12, 8), 256>>>(U, in_proj_w, P2);
    reduce_ctx<<<(B_SZ*E_SZ + 255)/256, 256>>>(P2, in_proj_b, CTX);

    // 8) attn_out = ctx @ Wo^T + bo
    sgemm_nt64_split<<<dim3(12, 12), 256>>>(E_SZ, 64, CTX, out_proj_w, P1);
    reduce_add_bias<<<(B_SZ*E_SZ + 255)/256, 256>>>(12, B_SZ*E_SZ, E_SZ, P1, out_proj_b, AO);

    // 9) broadcast * confidence
    broadcast_kernel<<<dim3(FULLN, B_SZ), 192>>>(AO, confidence, out);
}

// round 5
// speedup vs baseline: 5.4793x; 1.1979x over previous
#include <cuda_runtime.h>
#include <cuda_bf16.h>
#include <math.h>
#include <stdint.h>

#define B_SZ   64
#define FULLN  513
#define E_SZ   768
#define NB     32
#define GRIDSZ 8
#define NHEAD  12
#define HDIM   64
#define NP     (B_SZ * NB)      // 2048

// ---------------- scratch (device globals) ----------------
__device__ float g_S  [NP * E_SZ];        // trilinear samples (2048 x 768)
__device__ float g_T  [E_SZ * E_SZ];      // t rows h*64+b
__device__ float g_QH [E_SZ * E_SZ];      // qh' rows h*64+b
__device__ float g_WS [E_SZ * E_SZ];      // attn-weighted S, rows h*64+b
__device__ float g_U  [E_SZ * E_SZ];      // ws @ Ws^T + bs
__device__ float g_AO [B_SZ * E_SZ];
__device__ float g_P1 [4 * B_SZ * E_SZ];      // M=64 GEMM partials (4 splits)
__device__ float g_P2 [12 * 4 * 64 * 64];     // per-head ctx partials
__device__ float g_WsT[E_SZ * E_SZ];          // sample_w transposed
__device__ float g_WkT[E_SZ * E_SZ];          // Wk transposed

// ================= tensor-core helpers (sm_80+ PTX) =================
__device__ __forceinline__ uint32_t smem_u32(const void* p) {
    uint32_t a;
    asm("{ .reg .u64 t; cvta.to.shared.u64 t, %1; cvt.u32.u64 %0, t; }" : "=r"(a) : "l"(p));
    return a;
}
__device__ __forceinline__ void ldsm4(uint32_t* r, uint32_t addr) {
    asm volatile("ldmatrix.sync.aligned.m8n8.x4.shared.b16 {%0,%1,%2,%3}, [%4];"
        : "=r"(r[0]), "=r"(r[1]), "=r"(r[2]), "=r"(r[3]) : "r"(addr));
}
__device__ __forceinline__ void mma16816(float* d, const uint32_t* a, const uint32_t* b) {
    asm volatile("mma.sync.aligned.m16n8k16.row.col.f32.bf16.bf16.f32 "
        "{%0,%1,%2,%3}, {%4,%5,%6,%7}, {%8,%9}, {%0,%1,%2,%3};"
        : "+f"(d[0]), "+f"(d[1]), "+f"(d[2]), "+f"(d[3])
        : "r"(a[0]), "r"(a[1]), "r"(a[2]), "r"(a[3]), "r"(b[0]), "r"(b[1]));
}
__device__ __forceinline__ void cvt_hl(float4 v, uint2& hi, uint2& lo) {
    __nv_bfloat16 h0 = __float2bfloat16(v.x), h1 = __float2bfloat16(v.y);
    __nv_bfloat16 h2 = __float2bfloat16(v.z), h3 = __float2bfloat16(v.w);
    __nv_bfloat16 l0 = __float2bfloat16(v.x - __bfloat162float(h0));
    __nv_bfloat16 l1 = __float2bfloat16(v.y - __bfloat162float(h1));
    __nv_bfloat16 l2 = __float2bfloat16(v.z - __bfloat162float(h2));
    __nv_bfloat16 l3 = __float2bfloat16(v.w - __bfloat162float(h3));
    __nv_bfloat162 hp0 = __halves2bfloat162(h0, h1), hp1 = __halves2bfloat162(h2, h3);
    __nv_bfloat162 lp0 = __halves2bfloat162(l0, l1), lp1 = __halves2bfloat162(l2, l3);
    hi = make_uint2(*(uint32_t*)&hp0, *(uint32_t*)&hp1);
    lo = make_uint2(*(uint32_t*)&lp0, *(uint32_t*)&lp1);
}

#define PITCH   144
#define A_H_OFF 0
#define A_L_OFF 9216
#define B_H_OFF 18432
#define B_L_OFF 27648
#define TILE_SMEM 36864

__device__ __forceinline__ void store_pair(char* sm, int base_h, int base_l,
                                           int row, int c4, float4 v) {
    uint2 hi, lo;
    cvt_hl(v, hi, lo);
    *(uint2*)(sm + base_h + row * PITCH + c4 * 8) = hi;
    *(uint2*)(sm + base_l + row * PITCH + c4 * 8) = lo;
}

// full 64-K tile compute: 4 ks steps x (2 mi x 4 ni) x 3 split-terms
__device__ __forceinline__ void mma_tile64(uint32_t sb, int wm, int wn, int lane,
                                           float acc[2][4][4]) {
    #pragma unroll
    for (int ks = 0; ks < 4; ks++) {
        uint32_t a_h[2][4], a_l[2][4], b_h[4][2], b_l[4][2];
        #pragma unroll
        for (int mi = 0; mi < 2; mi++) {
            uint32_t r  = wm + mi * 16 + (lane & 15);
            uint32_t cb = ks * 32 + ((lane >> 4) << 4);
            ldsm4(a_h[mi], sb + A_H_OFF + r * PITCH + cb);
            ldsm4(a_l[mi], sb + A_L_OFF + r * PITCH + cb);
        }
        #pragma unroll
        for (int g = 0; g < 2; g++) {
            uint32_t n  = wn + g * 16 + (lane & 7) + (((lane >> 4) & 1) << 3);
            uint32_t cb = ks * 32 + (((lane >> 3) & 1) << 4);
            uint32_t t[4];
            ldsm4(t, sb + B_H_OFF + n * PITCH + cb);
            b_h[g*2][0] = t[0]; b_h[g*2][1] = t[1];
            b_h[g*2+1][0] = t[2]; b_h[g*2+1][1] = t[3];
            ldsm4(t, sb + B_L_OFF + n * PITCH + cb);
            b_l[g*2][0] = t[0]; b_l[g*2][1] = t[1];
            b_l[g*2+1][0] = t[2]; b_l[g*2+1][1] = t[3];
        }
        #pragma unroll
        for (int mi = 0; mi < 2; mi++)
            #pragma unroll
            for (int ni = 0; ni < 4; ni++) {
                mma16816(acc[mi][ni], a_h[mi], b_h[ni]);
                mma16816(acc[mi][ni], a_h[mi], b_l[ni]);
                mma16816(acc[mi][ni], a_l[mi], b_h[ni]);
            }
    }
}

// ---------------------------------------------------------------
// Generic HMMA NT GEMM: C = A @ B^T (+bias). CTA tile 64x64.
// grid (ntiles, mtiles, ksplits). If gridDim.z>1 writes partials at
// C + z*64*768 (M must be 64) and bias must be nullptr.
// Register-staged double buffering over 64-wide K iters.
// ---------------------------------------------------------------
__global__ __launch_bounds__(128)
void hmma_nt(const float* __restrict__ A,
             const float* __restrict__ B,
             const float* __restrict__ bias,
             float* __restrict__ C,
             int niter)
{
    __shared__ __align__(16) char sm[TILE_SMEM];
    const int tid  = threadIdx.x;
    const int wid  = tid >> 5, lane = tid & 31;
    const int bm   = blockIdx.y * 64, bn = blockIdx.x * 64;
    const int wm   = (wid & 1) * 32, wn = (wid >> 1) * 32;
    const int kbase = blockIdx.z * niter * 64;
    const uint32_t sb = smem_u32(sm);

    float acc[2][4][4] = {};
    float4 pa[8], pb[8];

    // prefetch first tile
    #pragma unroll
    for (int j = 0; j < 8; j++) {
        int fid = tid + j * 128;
        int row = fid >> 4, c4 = fid & 15;
        pa[j] = *(const float4*)(A + (size_t)(bm + row) * E_SZ + kbase + c4 * 4);
        pb[j] = *(const float4*)(B + (size_t)(bn + row) * E_SZ + kbase + c4 * 4);
    }

    for (int it = 0; it < niter; it++) {
        #pragma unroll
        for (int j = 0; j < 8; j++) {
            int fid = tid + j * 128;
            int row = fid >> 4, c4 = fid & 15;
            store_pair(sm, A_H_OFF, A_L_OFF, row, c4, pa[j]);
            store_pair(sm, B_H_OFF, B_L_OFF, row, c4, pb[j]);
        }
        __syncthreads();
        if (it + 1 < niter) {
            int k0 = kbase + (it + 1) * 64;
            #pragma unroll
            for (int j = 0; j < 8; j++) {
                int fid = tid + j * 128;
                int row = fid >> 4, c4 = fid & 15;
                pa[j] = *(const float4*)(A + (size_t)(bm + row) * E_SZ + k0 + c4 * 4);
                pb[j] = *(const float4*)(B + (size_t)(bn + row) * E_SZ + k0 + c4 * 4);
            }
        }
        mma_tile64(sb, wm, wn, lane, acc);
        __syncthreads();
    }

    float* Cp = C + (size_t)blockIdx.z * 64 * E_SZ;
    #pragma unroll
    for (int mi = 0; mi < 2; mi++) {
        int r0 = bm + wm + mi * 16 + (lane >> 2);
        #pragma unroll
        for (int ni = 0; ni < 4; ni++) {
            int c0 = bn + wn + ni * 8 + (lane & 3) * 2;
            float bb0 = bias ? bias[c0] : 0.f;
            float bb1 = bias ? bias[c0 + 1] : 0.f;
            *(float2*)(Cp + (size_t)r0 * E_SZ + c0) =
                make_float2(acc[mi][ni][0] + bb0, acc[mi][ni][1] + bb1);
            *(float2*)(Cp + (size_t)(r0 + 8) * E_SZ + c0) =
                make_float2(acc[mi][ni][2] + bb0, acc[mi][ni][3] + bb1);
        }
    }
}

// ---------------------------------------------------------------
// thead HMMA: T[h*64+b, e] = sum_d q[b,h*64+d] * Wk[h*64+d, e]
// A fused from q partials: q = sum_s P1[s] + bq. B = WkT (NT).
// grid (12 etiles, 12 heads), K=64 single iter.
// ---------------------------------------------------------------
__global__ __launch_bounds__(128)
void thead_hmma(const float* __restrict__ P1,
                const float* __restrict__ in_proj_b,
                const float* __restrict__ WkT,
                float* __restrict__ T)
{
    __shared__ __align__(16) char sm[TILE_SMEM];
    const int tid  = threadIdx.x;
    const int wid  = tid >> 5, lane = tid & 31;
    const int e0   = blockIdx.x * 64;
    const int h    = blockIdx.y;
    const int wm   = (wid & 1) * 32, wn = (wid >> 1) * 32;
    const uint32_t sb = smem_u32(sm);

    #pragma unroll
    for (int j = 0; j < 8; j++) {
        int fid = tid + j * 128;
        int row = fid >> 4, c4 = fid & 15;
        // A[b=row, d]: 4-way partial sum + bias
        const float* pbase = P1 + (size_t)row * E_SZ + h * 64 + c4 * 4;
        float4 v = *(const float4*)pbase;
        #pragma unroll
        for (int s = 1; s < 4; s++) {
            float4 p = *(const float4*)(pbase + (size_t)s * B_SZ * E_SZ);
            v.x += p.x; v.y += p.y; v.z += p.z; v.w += p.w;
        }
        float4 bq = *(const float4*)(in_proj_b + h * 64 + c4 * 4);
        v.x += bq.x; v.y += bq.y; v.z += bq.z; v.w += bq.w;
        store_pair(sm, A_H_OFF, A_L_OFF, row, c4, v);
        // B[e=row, d] = WkT[e0+row, h*64+d]
        float4 vb = *(const float4*)(WkT + (size_t)(e0 + row) * E_SZ + h * 64 + c4 * 4);
        store_pair(sm, B_H_OFF, B_L_OFF, row, c4, vb);
    }
    __syncthreads();

    float acc[2][4][4] = {};
    mma_tile64(sb, wm, wn, lane, acc);

    #pragma unroll
    for (int mi = 0; mi < 2; mi++) {
        int r0 = h * 64 + wm + mi * 16 + (lane >> 2);
        #pragma unroll
        for (int ni = 0; ni < 4; ni++) {
            int c0 = e0 + wn + ni * 8 + (lane & 3) * 2;
            *(float2*)(T + (size_t)r0 * E_SZ + c0) =
                make_float2(acc[mi][ni][0], acc[mi][ni][1]);
            *(float2*)(T + (size_t)(r0 + 8) * E_SZ + c0) =
                make_float2(acc[mi][ni][2], acc[mi][ni][3]);
        }
    }
}

// ---------------------------------------------------------------
// ctx HMMA partials: P2[(h*4+s)][b,d] = sum_{o in chunk} U[h*64+b,o]*Wv[h*64+d,o]
// grid (1, 12 heads, 4 splits), K chunk 192.
// ---------------------------------------------------------------
__global__ __launch_bounds__(128)
void ctx_hmma(const float* __restrict__ U,
              const float* __restrict__ in_proj_w,
              float* __restrict__ P2)
{
    __shared__ __align__(16) char sm[TILE_SMEM];
    const int tid  = threadIdx.x;
    const int wid  = tid >> 5, lane = tid & 31;
    const int h    = blockIdx.y, s = blockIdx.z;
    const int wm   = (wid & 1) * 32, wn = (wid >> 1) * 32;
    const uint32_t sb = smem_u32(sm);

    const float* A = U + (size_t)h * 64 * E_SZ;
    const float* B = in_proj_w + (size_t)(2 * E_SZ + h * 64) * E_SZ;

    float acc[2][4][4] = {};
    for (int it = 0; it < 3; it++) {
        int k0 = s * 192 + it * 64;
        #pragma unroll
        for (int j = 0; j < 8; j++) {
            int fid = tid + j * 128;
            int row = fid >> 4, c4 = fid & 15;
            float4 va = *(const float4*)(A + (size_t)row * E_SZ + k0 + c4 * 4);
            store_pair(sm, A_H_OFF, A_L_OFF, row, c4, va);
            float4 vb = *(const float4*)(B + (size_t)row * E_SZ + k0 + c4 * 4);
            store_pair(sm, B_H_OFF, B_L_OFF, row, c4, vb);
        }
        __syncthreads();
        mma_tile64(sb, wm, wn, lane, acc);
        __syncthreads();
    }

    float* Pp = P2 + (size_t)(h * 4 + s) * 4096;
    #pragma unroll
    for (int mi = 0; mi < 2; mi++) {
        int r0 = wm + mi * 16 + (lane >> 2);
        #pragma unroll
        for (int ni = 0; ni < 4; ni++) {
            int c0 = wn + ni * 8 + (lane & 3) * 2;
            *(float2*)(Pp + r0 * 64 + c0) =
                make_float2(acc[mi][ni][0], acc[mi][ni][1]);
            *(float2*)(Pp + (r0 + 8) * 64 + c0) =
                make_float2(acc[mi][ni][2], acc[mi][ni][3]);
        }
    }
}

// ---------------------------------------------------------------
// out-proj HMMA partials: A = ctx (fused from P2 partials + bv), B = Wo.
// grid (12 ntiles, 1, 4 splits), K chunk 192. Out: P1[s][b*768+n].
// ---------------------------------------------------------------
__global__ __launch_bounds__(128)
void outproj_hmma(const float* __restrict__ P2,
                  const float* __restrict__ in_proj_b,
                  const float* __restrict__ Wo,
                  float* __restrict__ P1)
{
    __shared__ __align__(16) char sm[TILE_SMEM];
    const int tid  = threadIdx.x;
    const int wid  = tid >> 5, lane = tid & 31;
    const int bn   = blockIdx.x * 64, s = blockIdx.z;
    const int wm   = (wid & 1) * 32, wn = (wid >> 1) * 32;
    const uint32_t sb = smem_u32(sm);

    float acc[2][4][4] = {};
    for (int it = 0; it < 3; it++) {
        int k0 = s * 192 + it * 64;
        int hh = k0 >> 6;                       // head block of this 64-col window
        #pragma unroll
        for (int j = 0; j < 8; j++) {
            int fid = tid + j * 128;
            int row = fid >> 4, c4 = fid & 15;
            // A[b=row, k] = sum_ss P2[(hh*4+ss)][row, d] + bv[k]
            const float* pbase = P2 + (size_t)(hh * 4) * 4096 + row * 64 + c4 * 4;
            float4 v = *(const float4*)pbase;
            #pragma unroll
            for (int ss = 1; ss < 4; ss++) {
                float4 p = *(const float4*)(pbase + (size_t)ss * 4096);
                v.x += p.x; v.y += p.y; v.z += p.z; v.w += p.w;
            }
            float4 bv = *(const float4*)(in_proj_b + 2 * E_SZ + k0 + c4 * 4);
            v.x += bv.x; v.y += bv.y; v.z += bv.z; v.w += bv.w;
            store_pair(sm, A_H_OFF, A_L_OFF, row, c4, v);
            float4 vb = *(const float4*)(Wo + (size_t)(bn + row) * E_SZ + k0 + c4 * 4);
            store_pair(sm, B_H_OFF, B_L_OFF, row, c4, vb);
        }
        __syncthreads();
        mma_tile64(sb, wm, wn, lane, acc);
        __syncthreads();
    }

    float* Pp = P1 + (size_t)s * B_SZ * E_SZ;
    #pragma unroll
    for (int mi = 0; mi < 2; mi++) {
        int r0 = wm + mi * 16 + (lane >> 2);
        #pragma unroll
        for (int ni = 0; ni < 4; ni++) {
            int c0 = bn + wn + ni * 8 + (lane & 3) * 2;
            *(float2*)(Pp + (size_t)r0 * E_SZ + c0) =
                make_float2(acc[mi][ni][0], acc[mi][ni][1]);
            *(float2*)(Pp + (size_t)(r0 + 8) * E_SZ + c0) =
                make_float2(acc[mi][ni][2], acc[mi][ni][3]);
        }
    }
}

// ---------------------------------------------------------------
// reduce 4 partials + bias (compile-time unrolled)
// ---------------------------------------------------------------
__global__ __launch_bounds__(256)
void reduce4_bias(const float* __restrict__ P,
                  const float* __restrict__ bias,
                  float* __restrict__ C)
{
    int idx = blockIdx.x * 256 + threadIdx.x;
    if (idx >= B_SZ * E_SZ) return;
    float a0 = P[idx];
    float a1 = P[(size_t)B_SZ * E_SZ + idx];
    float a2 = P[(size_t)2 * B_SZ * E_SZ + idx];
    float a3 = P[(size_t)3 * B_SZ * E_SZ + idx];
    C[idx] = (a0 + a1) + (a2 + a3) + bias[idx % E_SZ];
}

// ---------------------------------------------------------------
// transpose both weight matrices in one launch (z selects source)
// ---------------------------------------------------------------
__global__ __launch_bounds__(256)
void transpose2(const float* __restrict__ Ws, const float* __restrict__ Wk,
                float* __restrict__ WsT, float* __restrict__ WkT)
{
    __shared__ float t[32][33];
    const float* A  = blockIdx.z ? Wk : Ws;
    float* At       = blockIdx.z ? WkT : WsT;
    const int bx = blockIdx.x * 32, by = blockIdx.y * 32;
    #pragma unroll
    for (int i = 0; i < 32; i += 8)
        t[threadIdx.y + i][threadIdx.x] = A[(size_t)(by + threadIdx.y + i) * E_SZ + bx + threadIdx.x];
    __syncthreads();
    #pragma unroll
    for (int i = 0; i < 32; i += 8)
        At[(size_t)(bx + threadIdx.y + i) * E_SZ + by + threadIdx.x] = t[threadIdx.x][threadIdx.y + i];
}

// ---------------------------------------------------------------
// 1) Trilinear border sampling
// ---------------------------------------------------------------
__global__ __launch_bounds__(192)
void gather_kernel(const float* __restrict__ x,
                   const float* __restrict__ bc,
                   const float* __restrict__ off,
                   float* __restrict__ S)
{
    const int bp = blockIdx.x;
    const int b  = bp >> 5;
    const int p  = bp & 31;

    float cx = fminf(fmaxf(bc[p*3+0] + off[bp*3+0], -1.f), 1.f);
    float cy = fminf(fmaxf(bc[p*3+1] + off[bp*3+1], -1.f), 1.f);
    float cz = fminf(fmaxf(bc[p*3+2] + off[bp*3+2], -1.f), 1.f);

    float ix = (cx + 1.0f) * 0.5f * (GRIDSZ - 1);
    float iy = (cy + 1.0f) * 0.5f * (GRIDSZ - 1);
    float iz = (cz + 1.0f) * 0.5f * (GRIDSZ - 1);

    float fx = floorf(ix), fy = floorf(iy), fz = floorf(iz);
    float wx = ix - fx, wy = iy - fy, wz = iz - fz;

    int x0 = min(max((int)fx, 0), GRIDSZ-1);
    int y0 = min(max((int)fy, 0), GRIDSZ-1);
    int z0 = min(max((int)fz, 0), GRIDSZ-1);
    int x1 = min(x0 + 1, GRIDSZ-1);
    int y1 = min(y0 + 1, GRIDSZ-1);
    int z1 = min(z0 + 1, GRIDSZ-1);

    const float* xb = x + ((size_t)b * FULLN + 1) * E_SZ;

    int idx[8];
    idx[0] = (((z0*GRIDSZ)+y0)*GRIDSZ + x0) * E_SZ;
    idx[1] = (((z0*GRIDSZ)+y0)*GRIDSZ + x1) * E_SZ;
    idx[2] = (((z0*GRIDSZ)+y1)*GRIDSZ + x0) * E_SZ;
    idx[3] = (((z0*GRIDSZ)+y1)*GRIDSZ + x1) * E_SZ;
    idx[4] = (((z1*GRIDSZ)+y0)*GRIDSZ + x0) * E_SZ;
    idx[5] = (((z1*GRIDSZ)+y0)*GRIDSZ + x1) * E_SZ;
    idx[6] = (((z1*GRIDSZ)+y1)*GRIDSZ + x0) * E_SZ;
    idx[7] = (((z1*GRIDSZ)+y1)*GRIDSZ + x1) * E_SZ;

    float w[8];
    w[0] = (1-wz)*(1-wy)*(1-wx);
    w[1] = (1-wz)*(1-wy)*wx;
    w[2] = (1-wz)*wy*(1-wx);
    w[3] = (1-wz)*wy*wx;
    w[4] = wz*(1-wy)*(1-wx);
    w[5] = wz*(1-wy)*wx;
    w[6] = wz*wy*(1-wx);
    w[7] = wz*wy*wx;

    float4* out = (float4*)(S + (size_t)bp * E_SZ);
    const int c = threadIdx.x;
    float4 acc = make_float4(0.f,0.f,0.f,0.f);
    #pragma unroll
    for (int i = 0; i < 8; i++) {
        float4 v = ((const float4*)(xb + idx[i]))[c];
        acc.x = fmaf(w[i], v.x, acc.x);
        acc.y = fmaf(w[i], v.y, acc.y);
        acc.z = fmaf(w[i], v.z, acc.z);
        acc.w = fmaf(w[i], v.w, acc.w);
    }
    out[c] = acc;
}

// ---------------------------------------------------------------
// Fused attention: scores + softmax + weighted S. grid (64 b, 2 head-halves)
// ---------------------------------------------------------------
#define HGRP 6
__global__ __launch_bounds__(512)
void attn_fuse_kernel(const float* __restrict__ QH,
                      const float* __restrict__ S,
                      float* __restrict__ WS)
{
    extern __shared__ float smf[];
    float* Ssm = smf;                   // 32*768
    float* sc  = smf + NB * E_SZ;       // HGRP*32
    float* at  = sc + HGRP * NB;        // HGRP*32

    const int b  = blockIdx.x;
    const int h0 = blockIdx.y * HGRP;
    const int t  = threadIdx.x;

    {
        const float4* src = (const float4*)(S + (size_t)b * NB * E_SZ);
        float4* dst = (float4*)Ssm;
        for (int i = t; i < NB * E_SZ / 4; i += 512) dst[i] = src[i];
    }
    __syncthreads();

    const int w = t >> 5, lane = t & 31;

    for (int j = w; j < HGRP * NB; j += 16) {
        int h = h0 + (j >> 5), p = j & 31;
        const float* qr = QH + (size_t)(h*64 + b) * E_SZ;
        const float* sr = Ssm + p * E_SZ;
        float acc = 0.f;
        for (int c = lane; c < E_SZ; c += 32)
            acc = fmaf(qr[c], sr[c], acc);
        #pragma unroll
        for (int o = 16; o; o >>= 1) acc += __shfl_xor_sync(0xffffffffu, acc, o);
        if (lane == 0) sc[j] = acc * 0.125f;
    }
    __syncthreads();

    if (w < HGRP) {
        float s = sc[w*32 + lane];
        float m = s;
        #pragma unroll
        for (int o = 16; o; o >>= 1) m = fmaxf(m, __shfl_xor_sync(0xffffffffu, m, o));
        float e = __expf(s - m);
        float sum = e;
        #pragma unroll
        for (int o = 16; o; o >>= 1) sum += __shfl_xor_sync(0xffffffffu, sum, o);
        at[w*32 + lane] = e / sum;
    }
    __syncthreads();

    for (int idx = t; idx < HGRP * E_SZ; idx += 512) {
        int hl = idx / E_SZ, c = idx - hl * E_SZ;
        float acc = 0.f;
        #pragma unroll
        for (int p = 0; p < NB; p++)
            acc = fmaf(at[hl*32 + p], Ssm[p * E_SZ + c], acc);
        WS[(size_t)((h0 + hl)*64 + b) * E_SZ + c] = acc;
    }
}

// ---------------------------------------------------------------
// Broadcast * confidence
// ---------------------------------------------------------------
__global__ __launch_bounds__(192)
void broadcast_kernel(const float* __restrict__ ao,
                      const float* __restrict__ conf,
                      float* __restrict__ out)
{
    const int n = blockIdx.x;
    const int b = blockIdx.y;
    const float cf = conf[b];
    const float4* src = (const float4*)(ao + (size_t)b * E_SZ);
    float4* dst = (float4*)(out + ((size_t)b * FULLN + n) * E_SZ);
    float4 v = src[threadIdx.x];
    v.x *= cf; v.y *= cf; v.z *= cf; v.w *= cf;
    dst[threadIdx.x] = v;
}

// ---------------------------------------------------------------
extern "C" void kernel_launch(void* const* d_in, const int* in_sizes, int n_in,
                              void* d_out, int out_size)
{
    const float* x           = (const float*)d_in[0];
    const float* bio_embed   = (const float*)d_in[1];
    const float* base_coords = (const float*)d_in[2];
    const float* offsets     = (const float*)d_in[3];
    const float* confidence  = (const float*)d_in[4];
    const float* sample_w    = (const float*)d_in[5];
    const float* sample_b    = (const float*)d_in[6];
    const float* in_proj_w   = (const float*)d_in[7];
    const float* in_proj_b   = (const float*)d_in[8];
    const float* out_proj_w  = (const float*)d_in[9];
    const float* out_proj_b  = (const float*)d_in[10];
    float* out = (float*)d_out;

    float *S, *T, *QH, *WS, *U, *AO, *P1, *P2, *WsT, *WkT;
    cudaGetSymbolAddress((void**)&S,   g_S);
    cudaGetSymbolAddress((void**)&T,   g_T);
    cudaGetSymbolAddress((void**)&QH,  g_QH);
    cudaGetSymbolAddress((void**)&WS,  g_WS);
    cudaGetSymbolAddress((void**)&U,   g_U);
    cudaGetSymbolAddress((void**)&AO,  g_AO);
    cudaGetSymbolAddress((void**)&P1,  g_P1);
    cudaGetSymbolAddress((void**)&P2,  g_P2);
    cudaGetSymbolAddress((void**)&WsT, g_WsT);
    cudaGetSymbolAddress((void**)&WkT, g_WkT);

    const int attn_smem = (NB * E_SZ + 2 * HGRP * NB) * sizeof(float);
    cudaFuncSetAttribute(attn_fuse_kernel,
                         cudaFuncAttributeMaxDynamicSharedMemorySize, attn_smem);

    // 0) transpose Ws and Wk
    transpose2<<<dim3(24, 24, 2), dim3(32, 8)>>>(
        sample_w, in_proj_w + (size_t)E_SZ * E_SZ, WsT, WkT);

    // 1) trilinear gather -> S
    gather_kernel<<<NP, 192>>>(x, base_coords, offsets, S);

    // 2) q partials: P1[s] = bio @ Wq^T (K-split 4)
    hmma_nt<<<dim3(12, 1, 4), 128>>>(bio_embed, in_proj_w, nullptr, P1, 3);

    // 3) T[h*64+b,:] = (sum P1 + bq)_h @ Wk_h  (per-head, fused reduce)
    thead_hmma<<<dim3(12, 12), 128>>>(P1, in_proj_b, WkT, T);

    // 4) QH = T @ Ws  (NT against WsT)
    hmma_nt<<<dim3(12, 12, 1), 128>>>(T, WsT, nullptr, QH, 12);

    // 5) fused scores + softmax + weighted-S
    attn_fuse_kernel<<<dim3(B_SZ, 2), 512, attn_smem>>>(QH, S, WS);

    // 6) U = WS @ Ws^T + bs
    hmma_nt<<<dim3(12, 12, 1), 128>>>(WS, sample_w, sample_b, U, 12);

    // 7) ctx partials per head (K-split 4)
    ctx_hmma<<<dim3(1, 12, 4), 128>>>(U, in_proj_w, P2);

    // 8) out-proj partials (fused ctx reduce + bv)
    outproj_hmma<<<dim3(12, 1, 4), 128>>>(P2, in_proj_b, out_proj_w, P1);

    // 9) AO = sum P1 + bo
    reduce4_bias<<<(B_SZ*E_SZ + 255)/256, 256>>>(P1, out_proj_b, AO);

    // 10) broadcast * confidence
    broadcast_kernel<<<dim3(FULLN, B_SZ), 192>>>(AO, confidence, out);
}

// round 6
// speedup vs baseline: 5.6961x; 1.0396x over previous
#include <cuda_runtime.h>
#include <cuda_bf16.h>
#include <math.h>
#include <stdint.h>

#define B_SZ   64
#define FULLN  513
#define E_SZ   768
#define NB     32
#define GRIDSZ 8
#define NHEAD  12
#define HDIM   64
#define NP     (B_SZ * NB)      // 2048

// ---------------- scratch (device globals) ----------------
__device__ float g_S  [NP * E_SZ];        // trilinear samples (2048 x 768)
__device__ float g_T  [E_SZ * E_SZ];      // t rows h*64+b
__device__ float g_QH [E_SZ * E_SZ];      // qh' rows h*64+b
__device__ float g_WS [E_SZ * E_SZ];      // attn-weighted S, rows h*64+b
__device__ float g_U  [E_SZ * E_SZ];      // ws @ Ws^T + bs
__device__ float g_P1 [4 * B_SZ * E_SZ];      // M=64 GEMM partials (4 splits)
__device__ float g_P2 [12 * 4 * 64 * 64];     // per-head ctx partials
__device__ float g_WsT[E_SZ * E_SZ];          // sample_w transposed
__device__ float g_WkT[E_SZ * E_SZ];          // Wk transposed

// ================= tensor-core helpers (sm_80+ PTX) =================
__device__ __forceinline__ uint32_t smem_u32(const void* p) {
    uint32_t a;
    asm("{ .reg .u64 t; cvta.to.shared.u64 t, %1; cvt.u32.u64 %0, t; }" : "=r"(a) : "l"(p));
    return a;
}
__device__ __forceinline__ void ldsm4(uint32_t* r, uint32_t addr) {
    asm volatile("ldmatrix.sync.aligned.m8n8.x4.shared.b16 {%0,%1,%2,%3}, [%4];"
        : "=r"(r[0]), "=r"(r[1]), "=r"(r[2]), "=r"(r[3]) : "r"(addr));
}
__device__ __forceinline__ void mma16816(float* d, const uint32_t* a, const uint32_t* b) {
    asm volatile("mma.sync.aligned.m16n8k16.row.col.f32.bf16.bf16.f32 "
        "{%0,%1,%2,%3}, {%4,%5,%6,%7}, {%8,%9}, {%0,%1,%2,%3};"
        : "+f"(d[0]), "+f"(d[1]), "+f"(d[2]), "+f"(d[3])
        : "r"(a[0]), "r"(a[1]), "r"(a[2]), "r"(a[3]), "r"(b[0]), "r"(b[1]));
}
__device__ __forceinline__ void cvt_hl(float4 v, uint2& hi, uint2& lo) {
    __nv_bfloat16 h0 = __float2bfloat16(v.x), h1 = __float2bfloat16(v.y);
    __nv_bfloat16 h2 = __float2bfloat16(v.z), h3 = __float2bfloat16(v.w);
    __nv_bfloat16 l0 = __float2bfloat16(v.x - __bfloat162float(h0));
    __nv_bfloat16 l1 = __float2bfloat16(v.y - __bfloat162float(h1));
    __nv_bfloat16 l2 = __float2bfloat16(v.z - __bfloat162float(h2));
    __nv_bfloat16 l3 = __float2bfloat16(v.w - __bfloat162float(h3));
    __nv_bfloat162 hp0 = __halves2bfloat162(h0, h1), hp1 = __halves2bfloat162(h2, h3);
    __nv_bfloat162 lp0 = __halves2bfloat162(l0, l1), lp1 = __halves2bfloat162(l2, l3);
    hi = make_uint2(*(uint32_t*)&hp0, *(uint32_t*)&hp1);
    lo = make_uint2(*(uint32_t*)&lp0, *(uint32_t*)&lp1);
}

#define PITCH   144
#define A_H_OFF 0
#define A_L_OFF 9216
#define B_H_OFF 18432
#define B_L_OFF 27648
#define TILE_SMEM 36864

__device__ __forceinline__ void store_pair(char* sm, int base_h, int base_l,
                                           int row, int c4, float4 v) {
    uint2 hi, lo;
    cvt_hl(v, hi, lo);
    *(uint2*)(sm + base_h + row * PITCH + c4 * 8) = hi;
    *(uint2*)(sm + base_l + row * PITCH + c4 * 8) = lo;
}

// 64-K tile compute, 8 warps: warp tile 16x32. wm = (wid&3)*16, wn = (wid>>2)*32.
__device__ __forceinline__ void mma_tile64_8w(uint32_t sb, int wm, int wn, int lane,
                                              float acc[4][4]) {
    #pragma unroll
    for (int ks = 0; ks < 4; ks++) {
        uint32_t a_h[4], a_l[4], b_h[4][2], b_l[4][2];
        {
            uint32_t r  = wm + (lane & 15);
            uint32_t cb = ks * 32 + ((lane >> 4) << 4);
            ldsm4(a_h, sb + A_H_OFF + r * PITCH + cb);
            ldsm4(a_l, sb + A_L_OFF + r * PITCH + cb);
        }
        #pragma unroll
        for (int g = 0; g < 2; g++) {
            uint32_t n  = wn + g * 16 + (lane & 7) + (((lane >> 4) & 1) << 3);
            uint32_t cb = ks * 32 + (((lane >> 3) & 1) << 4);
            uint32_t t[4];
            ldsm4(t, sb + B_H_OFF + n * PITCH + cb);
            b_h[g*2][0] = t[0]; b_h[g*2][1] = t[1];
            b_h[g*2+1][0] = t[2]; b_h[g*2+1][1] = t[3];
            ldsm4(t, sb + B_L_OFF + n * PITCH + cb);
            b_l[g*2][0] = t[0]; b_l[g*2][1] = t[1];
            b_l[g*2+1][0] = t[2]; b_l[g*2+1][1] = t[3];
        }
        #pragma unroll
        for (int ni = 0; ni < 4; ni++) {
            mma16816(acc[ni], a_h, b_h[ni]);
            mma16816(acc[ni], a_h, b_l[ni]);
            mma16816(acc[ni], a_l, b_h[ni]);
        }
    }
}

// ---------------------------------------------------------------
// Generic HMMA NT GEMM: C = A @ B^T (+bias). CTA tile 64x64, 256 thr.
// grid (ntiles, mtiles, ksplits). gridDim.z>1 -> partials (M must be 64).
// ---------------------------------------------------------------
__global__ __launch_bounds__(256)
void hmma_nt(const float* __restrict__ A,
             const float* __restrict__ B,
             const float* __restrict__ bias,
             float* __restrict__ C,
             int niter)
{
    __shared__ __align__(16) char sm[TILE_SMEM];
    const int tid  = threadIdx.x;
    const int wid  = tid >> 5, lane = tid & 31;
    const int bm   = blockIdx.y * 64, bn = blockIdx.x * 64;
    const int wm   = (wid & 3) * 16, wn = (wid >> 2) * 32;
    const int kbase = blockIdx.z * niter * 64;
    const uint32_t sb = smem_u32(sm);

    float acc[4][4] = {};
    float4 pa[4], pb[4];

    #pragma unroll
    for (int j = 0; j < 4; j++) {
        int fid = tid + j * 256;
        int row = fid >> 4, c4 = fid & 15;
        pa[j] = *(const float4*)(A + (size_t)(bm + row) * E_SZ + kbase + c4 * 4);
        pb[j] = *(const float4*)(B + (size_t)(bn + row) * E_SZ + kbase + c4 * 4);
    }

    for (int it = 0; it < niter; it++) {
        #pragma unroll
        for (int j = 0; j < 4; j++) {
            int fid = tid + j * 256;
            int row = fid >> 4, c4 = fid & 15;
            store_pair(sm, A_H_OFF, A_L_OFF, row, c4, pa[j]);
            store_pair(sm, B_H_OFF, B_L_OFF, row, c4, pb[j]);
        }
        __syncthreads();
        if (it + 1 < niter) {
            int k0 = kbase + (it + 1) * 64;
            #pragma unroll
            for (int j = 0; j < 4; j++) {
                int fid = tid + j * 256;
                int row = fid >> 4, c4 = fid & 15;
                pa[j] = *(const float4*)(A + (size_t)(bm + row) * E_SZ + k0 + c4 * 4);
                pb[j] = *(const float4*)(B + (size_t)(bn + row) * E_SZ + k0 + c4 * 4);
            }
        }
        mma_tile64_8w(sb, wm, wn, lane, acc);
        __syncthreads();
    }

    float* Cp = C + (size_t)blockIdx.z * 64 * E_SZ;
    {
        int r0 = bm + wm + (lane >> 2);
        #pragma unroll
        for (int ni = 0; ni < 4; ni++) {
            int c0 = bn + wn + ni * 8 + (lane & 3) * 2;
            float bb0 = bias ? bias[c0] : 0.f;
            float bb1 = bias ? bias[c0 + 1] : 0.f;
            *(float2*)(Cp + (size_t)r0 * E_SZ + c0) =
                make_float2(acc[ni][0] + bb0, acc[ni][1] + bb1);
            *(float2*)(Cp + (size_t)(r0 + 8) * E_SZ + c0) =
                make_float2(acc[ni][2] + bb0, acc[ni][3] + bb1);
        }
    }
}

// ---------------------------------------------------------------
// thead HMMA: T[h*64+b, e] = sum_d (sum_s P1[s][b,h*64+d] + bq) * WkT[e, h*64+d]
// grid (12 etiles, 12 heads), 256 thr, K=64 single iter.
// ---------------------------------------------------------------
__global__ __launch_bounds__(256)
void thead_hmma(const float* __restrict__ P1,
                const float* __restrict__ in_proj_b,
                const float* __restrict__ WkT,
                float* __restrict__ T)
{
    __shared__ __align__(16) char sm[TILE_SMEM];
    const int tid  = threadIdx.x;
    const int wid  = tid >> 5, lane = tid & 31;
    const int e0   = blockIdx.x * 64;
    const int h    = blockIdx.y;
    const int wm   = (wid & 3) * 16, wn = (wid >> 2) * 32;
    const uint32_t sb = smem_u32(sm);

    #pragma unroll
    for (int j = 0; j < 4; j++) {
        int fid = tid + j * 256;
        int row = fid >> 4, c4 = fid & 15;
        const float* pbase = P1 + (size_t)row * E_SZ + h * 64 + c4 * 4;
        float4 v = *(const float4*)pbase;
        #pragma unroll
        for (int s = 1; s < 4; s++) {
            float4 p = *(const float4*)(pbase + (size_t)s * B_SZ * E_SZ);
            v.x += p.x; v.y += p.y; v.z += p.z; v.w += p.w;
        }
        float4 bq = *(const float4*)(in_proj_b + h * 64 + c4 * 4);
        v.x += bq.x; v.y += bq.y; v.z += bq.z; v.w += bq.w;
        store_pair(sm, A_H_OFF, A_L_OFF, row, c4, v);
        float4 vb = *(const float4*)(WkT + (size_t)(e0 + row) * E_SZ + h * 64 + c4 * 4);
        store_pair(sm, B_H_OFF, B_L_OFF, row, c4, vb);
    }
    __syncthreads();

    float acc[4][4] = {};
    mma_tile64_8w(sb, wm, wn, lane, acc);

    {
        int r0 = h * 64 + wm + (lane >> 2);
        #pragma unroll
        for (int ni = 0; ni < 4; ni++) {
            int c0 = e0 + wn + ni * 8 + (lane & 3) * 2;
            *(float2*)(T + (size_t)r0 * E_SZ + c0) =
                make_float2(acc[ni][0], acc[ni][1]);
            *(float2*)(T + (size_t)(r0 + 8) * E_SZ + c0) =
                make_float2(acc[ni][2], acc[ni][3]);
        }
    }
}

// ---------------------------------------------------------------
// ctx HMMA partials: P2[(h*4+s)][b,d] = sum_{o chunk} U[h*64+b,o]*Wv[h*64+d,o]
// grid (1, 12 heads, 4 splits), 256 thr, K chunk 192.
// ---------------------------------------------------------------
__global__ __launch_bounds__(256)
void ctx_hmma(const float* __restrict__ U,
              const float* __restrict__ in_proj_w,
              float* __restrict__ P2)
{
    __shared__ __align__(16) char sm[TILE_SMEM];
    const int tid  = threadIdx.x;
    const int wid  = tid >> 5, lane = tid & 31;
    const int h    = blockIdx.y, s = blockIdx.z;
    const int wm   = (wid & 3) * 16, wn = (wid >> 2) * 32;
    const uint32_t sb = smem_u32(sm);

    const float* A = U + (size_t)h * 64 * E_SZ;
    const float* B = in_proj_w + (size_t)(2 * E_SZ + h * 64) * E_SZ;

    float acc[4][4] = {};
    for (int it = 0; it < 3; it++) {
        int k0 = s * 192 + it * 64;
        #pragma unroll
        for (int j = 0; j < 4; j++) {
            int fid = tid + j * 256;
            int row = fid >> 4, c4 = fid & 15;
            float4 va = *(const float4*)(A + (size_t)row * E_SZ + k0 + c4 * 4);
            store_pair(sm, A_H_OFF, A_L_OFF, row, c4, va);
            float4 vb = *(const float4*)(B + (size_t)row * E_SZ + k0 + c4 * 4);
            store_pair(sm, B_H_OFF, B_L_OFF, row, c4, vb);
        }
        __syncthreads();
        mma_tile64_8w(sb, wm, wn, lane, acc);
        __syncthreads();
    }

    float* Pp = P2 + (size_t)(h * 4 + s) * 4096;
    {
        int r0 = wm + (lane >> 2);
        #pragma unroll
        for (int ni = 0; ni < 4; ni++) {
            int c0 = wn + ni * 8 + (lane & 3) * 2;
            *(float2*)(Pp + r0 * 64 + c0) = make_float2(acc[ni][0], acc[ni][1]);
            *(float2*)(Pp + (r0 + 8) * 64 + c0) = make_float2(acc[ni][2], acc[ni][3]);
        }
    }
}

// ---------------------------------------------------------------
// out-proj HMMA partials: A = ctx (fused P2 reduce + bv), B = Wo.
// grid (12 ntiles, 1, 4 splits), 256 thr, K chunk 192. Out: P1[s].
// ---------------------------------------------------------------
__global__ __launch_bounds__(256)
void outproj_hmma(const float* __restrict__ P2,
                  const float* __restrict__ in_proj_b,
                  const float* __restrict__ Wo,
                  float* __restrict__ P1)
{
    __shared__ __align__(16) char sm[TILE_SMEM];
    const int tid  = threadIdx.x;
    const int wid  = tid >> 5, lane = tid & 31;
    const int bn   = blockIdx.x * 64, s = blockIdx.z;
    const int wm   = (wid & 3) * 16, wn = (wid >> 2) * 32;
    const uint32_t sb = smem_u32(sm);

    float acc[4][4] = {};
    for (int it = 0; it < 3; it++) {
        int k0 = s * 192 + it * 64;
        int hh = k0 >> 6;
        #pragma unroll
        for (int j = 0; j < 4; j++) {
            int fid = tid + j * 256;
            int row = fid >> 4, c4 = fid & 15;
            const float* pbase = P2 + (size_t)(hh * 4) * 4096 + row * 64 + c4 * 4;
            float4 v = *(const float4*)pbase;
            #pragma unroll
            for (int ss = 1; ss < 4; ss++) {
                float4 p = *(const float4*)(pbase + (size_t)ss * 4096);
                v.x += p.x; v.y += p.y; v.z += p.z; v.w += p.w;
            }
            float4 bv = *(const float4*)(in_proj_b + 2 * E_SZ + k0 + c4 * 4);
            v.x += bv.x; v.y += bv.y; v.z += bv.z; v.w += bv.w;
            store_pair(sm, A_H_OFF, A_L_OFF, row, c4, v);
            float4 vb = *(const float4*)(Wo + (size_t)(bn + row) * E_SZ + k0 + c4 * 4);
            store_pair(sm, B_H_OFF, B_L_OFF, row, c4, vb);
        }
        __syncthreads();
        mma_tile64_8w(sb, wm, wn, lane, acc);
        __syncthreads();
    }

    float* Pp = P1 + (size_t)s * B_SZ * E_SZ;
    {
        int r0 = wm + (lane >> 2);
        #pragma unroll
        for (int ni = 0; ni < 4; ni++) {
            int c0 = bn + wn + ni * 8 + (lane & 3) * 2;
            *(float2*)(Pp + (size_t)r0 * E_SZ + c0) =
                make_float2(acc[ni][0], acc[ni][1]);
            *(float2*)(Pp + (size_t)(r0 + 8) * E_SZ + c0) =
                make_float2(acc[ni][2], acc[ni][3]);
        }
    }
}

// ---------------------------------------------------------------
// transpose both weight matrices in one launch (z selects source)
// ---------------------------------------------------------------
__global__ __launch_bounds__(256)
void transpose2(const float* __restrict__ Ws, const float* __restrict__ Wk,
                float* __restrict__ WsT, float* __restrict__ WkT)
{
    __shared__ float t[32][33];
    const float* A  = blockIdx.z ? Wk : Ws;
    float* At       = blockIdx.z ? WkT : WsT;
    const int bx = blockIdx.x * 32, by = blockIdx.y * 32;
    #pragma unroll
    for (int i = 0; i < 32; i += 8)
        t[threadIdx.y + i][threadIdx.x] = A[(size_t)(by + threadIdx.y + i) * E_SZ + bx + threadIdx.x];
    __syncthreads();
    #pragma unroll
    for (int i = 0; i < 32; i += 8)
        At[(size_t)(bx + threadIdx.y + i) * E_SZ + by + threadIdx.x] = t[threadIdx.x][threadIdx.y + i];
}

// ---------------------------------------------------------------
// Trilinear border sampling
// ---------------------------------------------------------------
__global__ __launch_bounds__(192)
void gather_kernel(const float* __restrict__ x,
                   const float* __restrict__ bc,
                   const float* __restrict__ off,
                   float* __restrict__ S)
{
    const int bp = blockIdx.x;
    const int b  = bp >> 5;
    const int p  = bp & 31;

    float cx = fminf(fmaxf(bc[p*3+0] + off[bp*3+0], -1.f), 1.f);
    float cy = fminf(fmaxf(bc[p*3+1] + off[bp*3+1], -1.f), 1.f);
    float cz = fminf(fmaxf(bc[p*3+2] + off[bp*3+2], -1.f), 1.f);

    float ix = (cx + 1.0f) * 0.5f * (GRIDSZ - 1);
    float iy = (cy + 1.0f) * 0.5f * (GRIDSZ - 1);
    float iz = (cz + 1.0f) * 0.5f * (GRIDSZ - 1);

    float fx = floorf(ix), fy = floorf(iy), fz = floorf(iz);
    float wx = ix - fx, wy = iy - fy, wz = iz - fz;

    int x0 = min(max((int)fx, 0), GRIDSZ-1);
    int y0 = min(max((int)fy, 0), GRIDSZ-1);
    int z0 = min(max((int)fz, 0), GRIDSZ-1);
    int x1 = min(x0 + 1, GRIDSZ-1);
    int y1 = min(y0 + 1, GRIDSZ-1);
    int z1 = min(z0 + 1, GRIDSZ-1);

    const float* xb = x + ((size_t)b * FULLN + 1) * E_SZ;

    int idx[8];
    idx[0] = (((z0*GRIDSZ)+y0)*GRIDSZ + x0) * E_SZ;
    idx[1] = (((z0*GRIDSZ)+y0)*GRIDSZ + x1) * E_SZ;
    idx[2] = (((z0*GRIDSZ)+y1)*GRIDSZ + x0) * E_SZ;
    idx[3] = (((z0*GRIDSZ)+y1)*GRIDSZ + x1) * E_SZ;
    idx[4] = (((z1*GRIDSZ)+y0)*GRIDSZ + x0) * E_SZ;
    idx[5] = (((z1*GRIDSZ)+y0)*GRIDSZ + x1) * E_SZ;
    idx[6] = (((z1*GRIDSZ)+y1)*GRIDSZ + x0) * E_SZ;
    idx[7] = (((z1*GRIDSZ)+y1)*GRIDSZ + x1) * E_SZ;

    float w[8];
    w[0] = (1-wz)*(1-wy)*(1-wx);
    w[1] = (1-wz)*(1-wy)*wx;
    w[2] = (1-wz)*wy*(1-wx);
    w[3] = (1-wz)*wy*wx;
    w[4] = wz*(1-wy)*(1-wx);
    w[5] = wz*(1-wy)*wx;
    w[6] = wz*wy*(1-wx);
    w[7] = wz*wy*wx;

    float4* out = (float4*)(S + (size_t)bp * E_SZ);
    const int c = threadIdx.x;
    float4 acc = make_float4(0.f,0.f,0.f,0.f);
    #pragma unroll
    for (int i = 0; i < 8; i++) {
        float4 v = ((const float4*)(xb + idx[i]))[c];
        acc.x = fmaf(w[i], v.x, acc.x);
        acc.y = fmaf(w[i], v.y, acc.y);
        acc.z = fmaf(w[i], v.z, acc.z);
        acc.w = fmaf(w[i], v.w, acc.w);
    }
    out[c] = acc;
}

// ---------------------------------------------------------------
// Fused attention: scores + softmax + weighted S. grid (64 b, 2 head-halves)
// ---------------------------------------------------------------
#define HGRP 6
__global__ __launch_bounds__(512)
void attn_fuse_kernel(const float* __restrict__ QH,
                      const float* __restrict__ S,
                      float* __restrict__ WS)
{
    extern __shared__ float smf[];
    float* Ssm = smf;                   // 32*768
    float* sc  = smf + NB * E_SZ;       // HGRP*32
    float* at  = sc + HGRP * NB;        // HGRP*32

    const int b  = blockIdx.x;
    const int h0 = blockIdx.y * HGRP;
    const int t  = threadIdx.x;

    {
        const float4* src = (const float4*)(S + (size_t)b * NB * E_SZ);
        float4* dst = (float4*)Ssm;
        for (int i = t; i < NB * E_SZ / 4; i += 512) dst[i] = src[i];
    }
    __syncthreads();

    const int w = t >> 5, lane = t & 31;

    for (int j = w; j < HGRP * NB; j += 16) {
        int h = h0 + (j >> 5), p = j & 31;
        const float* qr = QH + (size_t)(h*64 + b) * E_SZ;
        const float* sr = Ssm + p * E_SZ;
        float acc = 0.f;
        for (int c = lane; c < E_SZ; c += 32)
            acc = fmaf(qr[c], sr[c], acc);
        #pragma unroll
        for (int o = 16; o; o >>= 1) acc += __shfl_xor_sync(0xffffffffu, acc, o);
        if (lane == 0) sc[j] = acc * 0.125f;
    }
    __syncthreads();

    if (w < HGRP) {
        float s = sc[w*32 + lane];
        float m = s;
        #pragma unroll
        for (int o = 16; o; o >>= 1) m = fmaxf(m, __shfl_xor_sync(0xffffffffu, m, o));
        float e = __expf(s - m);
        float sum = e;
        #pragma unroll
        for (int o = 16; o; o >>= 1) sum += __shfl_xor_sync(0xffffffffu, sum, o);
        at[w*32 + lane] = e / sum;
    }
    __syncthreads();

    for (int idx = t; idx < HGRP * E_SZ; idx += 512) {
        int hl = idx / E_SZ, c = idx - hl * E_SZ;
        float acc = 0.f;
        #pragma unroll
        for (int p = 0; p < NB; p++)
            acc = fmaf(at[hl*32 + p], Ssm[p * E_SZ + c], acc);
        WS[(size_t)((h0 + hl)*64 + b) * E_SZ + c] = acc;
    }
}

// ---------------------------------------------------------------
// Fused reduce + broadcast: out[b,n,:] = (sum_s P1[s][b,:] + bo) * conf[b]
// grid (64 b, 19 n-groups of 27), 256 threads
// ---------------------------------------------------------------
__global__ __launch_bounds__(256)
void bcast_reduce_kernel(const float* __restrict__ P1,
                         const float* __restrict__ bo,
                         const float* __restrict__ conf,
                         float* __restrict__ out)
{
    __shared__ __align__(16) float ao[E_SZ];
    const int b  = blockIdx.x;
    const int n0 = blockIdx.y * 27;
    const int t  = threadIdx.x;
    const float cf = conf[b];

    for (int c = t; c < E_SZ; c += 256) {
        float a0 = P1[(size_t)b * E_SZ + c];
        float a1 = P1[(size_t)(B_SZ + b) * E_SZ + c];
        float a2 = P1[(size_t)(2 * B_SZ + b) * E_SZ + c];
        float a3 = P1[(size_t)(3 * B_SZ + b) * E_SZ + c];
        ao[c] = ((a0 + a1) + (a2 + a3) + bo[c]) * cf;
    }
    __syncthreads();

    const float4* src = (const float4*)ao;
    float4* dstb = (float4*)(out + ((size_t)b * FULLN + n0) * E_SZ);
    const int nrows = min(27, FULLN - n0);
    for (int i = t; i < nrows * 192; i += 256) {
        int r = i / 192, c = i - r * 192;
        dstb[(size_t)r * 192 + c] = src[c];
    }
}

// ---------------------------------------------------------------
extern "C" void kernel_launch(void* const* d_in, const int* in_sizes, int n_in,
                              void* d_out, int out_size)
{
    const float* x           = (const float*)d_in[0];
    const float* bio_embed   = (const float*)d_in[1];
    const float* base_coords = (const float*)d_in[2];
    const float* offsets     = (const float*)d_in[3];
    const float* confidence  = (const float*)d_in[4];
    const float* sample_w    = (const float*)d_in[5];
    const float* sample_b    = (const float*)d_in[6];
    const float* in_proj_w   = (const float*)d_in[7];
    const float* in_proj_b   = (const float*)d_in[8];
    const float* out_proj_w  = (const float*)d_in[9];
    const float* out_proj_b  = (const float*)d_in[10];
    float* out = (float*)d_out;

    float *S, *T, *QH, *WS, *U, *P1, *P2, *WsT, *WkT;
    cudaGetSymbolAddress((void**)&S,   g_S);
    cudaGetSymbolAddress((void**)&T,   g_T);
    cudaGetSymbolAddress((void**)&QH,  g_QH);
    cudaGetSymbolAddress((void**)&WS,  g_WS);
    cudaGetSymbolAddress((void**)&U,   g_U);
    cudaGetSymbolAddress((void**)&P1,  g_P1);
    cudaGetSymbolAddress((void**)&P2,  g_P2);
    cudaGetSymbolAddress((void**)&WsT, g_WsT);
    cudaGetSymbolAddress((void**)&WkT, g_WkT);

    const int attn_smem = (NB * E_SZ + 2 * HGRP * NB) * sizeof(float);
    cudaFuncSetAttribute(attn_fuse_kernel,
                         cudaFuncAttributeMaxDynamicSharedMemorySize, attn_smem);

    // 0) transpose Ws and Wk
    transpose2<<<dim3(24, 24, 2), dim3(32, 8)>>>(
        sample_w, in_proj_w + (size_t)E_SZ * E_SZ, WsT, WkT);

    // 1) trilinear gather -> S
    gather_kernel<<<NP, 192>>>(x, base_coords, offsets, S);

    // 2) q partials: P1[s] = bio @ Wq^T (K-split 4)
    hmma_nt<<<dim3(12, 1, 4), 256>>>(bio_embed, in_proj_w, nullptr, P1, 3);

    // 3) T[h*64+b,:] = (sum P1 + bq)_h @ Wk_h
    thead_hmma<<<dim3(12, 12), 256>>>(P1, in_proj_b, WkT, T);

    // 4) QH = T @ Ws
    hmma_nt<<<dim3(12, 12, 1), 256>>>(T, WsT, nullptr, QH, 12);

    // 5) fused scores + softmax + weighted-S
    attn_fuse_kernel<<<dim3(B_SZ, 2), 512, attn_smem>>>(QH, S, WS);

    // 6) U = WS @ Ws^T + bs
    hmma_nt<<<dim3(12, 12, 1), 256>>>(WS, sample_w, sample_b, U, 12);

    // 7) ctx partials per head (K-split 4)
    ctx_hmma<<<dim3(1, 12, 4), 256>>>(U, in_proj_w, P2);

    // 8) out-proj partials (fused ctx reduce + bv)
    outproj_hmma<<<dim3(12, 1, 4), 256>>>(P2, in_proj_b, out_proj_w, P1);

    // 9) fused reduce + broadcast * confidence
    bcast_reduce_kernel<<<dim3(B_SZ, 19), 256>>>(P1, out_proj_b, confidence, out);
}